// round 12
// baseline (speedup 1.0000x reference)
#include <cuda_runtime.h>
#include <cuda_fp16.h>
#include <math.h>
#include <stdint.h>

#define T_TOK 2048
#define H_DIM 2048
#define I_DIM 2048
#define E_NUM 16
#define TOPK  4
#define ROWS  (T_TOK*TOPK)

// ---------------- scratch ----------------
__device__ __half g_tnh[(size_t)T_TOK * H_DIM];
__device__ __half g_h1h[(size_t)ROWS * I_DIM];
__device__ float g_h2[(size_t)ROWS * H_DIM];
__device__ int   g_cnt[E_NUM];
__device__ int   g_off[E_NUM];
__device__ int   g_rowtok[ROWS];
__device__ float g_roww[ROWS];
__device__ int   g_tokrows[T_TOK * TOPK];
__device__ int   g_topidx[T_TOK * TOPK];
__device__ float g_topw[T_TOK * TOPK];

// ---------------- PTX helpers ----------------
__device__ __forceinline__ uint32_t smem_u32(const void* p) {
    uint32_t a;
    asm("{ .reg .u64 t; cvta.to.shared.u64 t, %1; cvt.u32.u64 %0, t; }" : "=r"(a) : "l"(p));
    return a;
}
__device__ __forceinline__ void ldsm_x4(uint32_t* r, uint32_t addr) {
    asm volatile("ldmatrix.sync.aligned.m8n8.x4.shared.b16 {%0,%1,%2,%3}, [%4];"
                 : "=r"(r[0]), "=r"(r[1]), "=r"(r[2]), "=r"(r[3]) : "r"(addr));
}
__device__ __forceinline__ void mma16816(float* d, const uint32_t* a, const uint32_t* b) {
    asm volatile("mma.sync.aligned.m16n8k16.row.col.f32.f16.f16.f32 "
                 "{%0,%1,%2,%3}, {%4,%5,%6,%7}, {%8,%9}, {%0,%1,%2,%3};"
                 : "+f"(d[0]), "+f"(d[1]), "+f"(d[2]), "+f"(d[3])
                 : "r"(a[0]), "r"(a[1]), "r"(a[2]), "r"(a[3]), "r"(b[0]), "r"(b[1]));
}
__device__ __forceinline__ uint32_t pkh2(float a, float b) {
    __half2 h = __floats2half2_rn(a, b);
    return *(uint32_t*)&h;
}
__device__ __forceinline__ void cp_async16(uint32_t dst, const void* src) {
    asm volatile("cp.async.cg.shared.global [%0], [%1], 16;" :: "r"(dst), "l"(src) : "memory");
}
__device__ __forceinline__ void cp_commit() {
    asm volatile("cp.async.commit_group;" ::: "memory");
}
__device__ __forceinline__ void cp_wait0() {
    asm volatile("cp.async.wait_group 0;" ::: "memory");
}

// ---------------- 1: fused RMSNorm + router ----------------
__global__ __launch_bounds__(256) void rms_router_kernel(
    const float* __restrict__ x, const float* __restrict__ scale,
    const float* __restrict__ gk, const float* __restrict__ gb)
{
    int t = blockIdx.x;
    int tid = threadIdx.x;
    const float* xr = x + (size_t)t * H_DIM;

    float4 v0 = *(const float4*)(xr + tid * 8);
    float4 v1 = *(const float4*)(xr + tid * 8 + 4);
    float ss = v0.x*v0.x + v0.y*v0.y + v0.z*v0.z + v0.w*v0.w
             + v1.x*v1.x + v1.y*v1.y + v1.z*v1.z + v1.w*v1.w;
    #pragma unroll
    for (int o = 16; o > 0; o >>= 1) ss += __shfl_down_sync(0xffffffffu, ss, o);
    __shared__ float warpsum[8];
    __shared__ float s_r;
    if ((tid & 31) == 0) warpsum[tid >> 5] = ss;
    __syncthreads();
    if (tid == 0) {
        float tot = 0.f;
        #pragma unroll
        for (int w = 0; w < 8; w++) tot += warpsum[w];
        s_r = 1.0f / sqrtf(tot / (float)H_DIM + 1e-5f);
    }
    __syncthreads();
    float r = s_r;

    float4 sc0 = *(const float4*)(scale + tid * 8);
    float4 sc1 = *(const float4*)(scale + tid * 8 + 4);
    float tn[8];
    tn[0] = v0.x*r*sc0.x; tn[1] = v0.y*r*sc0.y; tn[2] = v0.z*r*sc0.z; tn[3] = v0.w*r*sc0.w;
    tn[4] = v1.x*r*sc1.x; tn[5] = v1.y*r*sc1.y; tn[6] = v1.z*r*sc1.z; tn[7] = v1.w*r*sc1.w;

    __half hh[8];
    #pragma unroll
    for (int u = 0; u < 8; u++) hh[u] = __float2half(tn[u]);
    *(uint4*)(g_tnh + (size_t)t * H_DIM + tid * 8) = *(uint4*)hh;

    float ge[E_NUM];
    #pragma unroll
    for (int e = 0; e < E_NUM; e++) ge[e] = 0.f;
    #pragma unroll
    for (int u = 0; u < 8; u++) {
        const float4* wrow = (const float4*)(gk + (size_t)(tid * 8 + u) * E_NUM);
        float tv = tn[u];
        float4 a = wrow[0], b = wrow[1], c = wrow[2], d = wrow[3];
        ge[0]+=tv*a.x; ge[1]+=tv*a.y; ge[2]+=tv*a.z; ge[3]+=tv*a.w;
        ge[4]+=tv*b.x; ge[5]+=tv*b.y; ge[6]+=tv*b.z; ge[7]+=tv*b.w;
        ge[8]+=tv*c.x; ge[9]+=tv*c.y; ge[10]+=tv*c.z; ge[11]+=tv*c.w;
        ge[12]+=tv*d.x; ge[13]+=tv*d.y; ge[14]+=tv*d.z; ge[15]+=tv*d.w;
    }
    #pragma unroll
    for (int o = 16; o > 0; o >>= 1) {
        #pragma unroll
        for (int e = 0; e < E_NUM; e++) ge[e] += __shfl_down_sync(0xffffffffu, ge[e], o);
    }
    __shared__ float sg[8][E_NUM];
    if ((tid & 31) == 0) {
        #pragma unroll
        for (int e = 0; e < E_NUM; e++) sg[tid >> 5][e] = ge[e];
    }
    __syncthreads();
    __shared__ float s_logit[E_NUM];
    if (tid < E_NUM) {
        float v = gb[tid];
        #pragma unroll
        for (int w = 0; w < 8; w++) v += sg[w][tid];
        s_logit[tid] = v;
    }
    __syncthreads();
    if (tid == 0) {
        float vals[E_NUM];
        #pragma unroll
        for (int e = 0; e < E_NUM; e++) vals[e] = s_logit[e];
        int ids[TOPK]; float tv[TOPK];
        #pragma unroll
        for (int k = 0; k < TOPK; k++) {
            int bi = 0; float bv = -1e30f;
            #pragma unroll
            for (int e = 0; e < E_NUM; e++) if (vals[e] > bv) { bv = vals[e]; bi = e; }
            ids[k] = bi; tv[k] = bv; vals[bi] = -1e30f;
        }
        float m = tv[0], ex[TOPK], s = 0.f;
        #pragma unroll
        for (int k = 0; k < TOPK; k++) { ex[k] = expf(tv[k] - m); s += ex[k]; }
        float inv = 1.0f / s;
        #pragma unroll
        for (int k = 0; k < TOPK; k++) {
            g_topidx[t * TOPK + k] = ids[k];
            g_topw[t * TOPK + k]   = ex[k] * inv;
        }
    }
}

// ---------------- 2: route ----------------
__global__ __launch_bounds__(256) void route_kernel() {
    __shared__ int s_cnt[E_NUM];
    __shared__ int s_off[E_NUM];
    __shared__ int s_cur[E_NUM];
    int tid = threadIdx.x;
    if (tid < E_NUM) s_cnt[tid] = 0;
    __syncthreads();
    for (int i = tid; i < T_TOK * TOPK; i += 256)
        atomicAdd(&s_cnt[g_topidx[i]], 1);
    __syncthreads();
    if (tid == 0) {
        int acc = 0;
        for (int e = 0; e < E_NUM; e++) { s_off[e] = acc; s_cur[e] = acc; acc += s_cnt[e]; }
    }
    __syncthreads();
    if (tid < E_NUM) { g_cnt[tid] = s_cnt[tid]; g_off[tid] = s_off[tid]; }
    for (int i = tid; i < T_TOK * TOPK; i += 256) {
        int e = g_topidx[i];
        int pos = atomicAdd(&s_cur[e], 1);
        g_rowtok[pos] = i >> 2;
        g_roww[pos]   = g_topw[i];
        g_tokrows[i]  = pos;
    }
}

// ---------------- 3/4: grouped GEMMs: CTA 256m x 128n, 512 thr, 16 warps 4m x 4n ----------------
// Warp tile 64x32 (64 acc regs). A fp16 cp.async; B fp32 LDG -> fp16 STS (1 chunk/thread).
// B bytes amortized over 2x MACs vs 128-row CTA. Inactive warps skip ldsm/MMA.
#define ROWB 80
#define SM_A 0
#define SM_B 20480
#define BUF_BYTES 30720
#define DSMEM (2 * BUF_BYTES)

template <int MODE>
__global__ __launch_bounds__(512, 1) void moe_mma_kernel(
    const float* __restrict__ W, const float* __restrict__ bias)
{
    constexpr int NTOT = (MODE == 1) ? 2 * I_DIM : H_DIM;
    constexpr int KD = 2048;
    constexpr int NST = KD / 32;   // 64 stages

    // blockIdx.x = 256-row m-tile (consecutive CTAs share B via L2)
    int mt = blockIdx.x;
    int e = -1, cnt_e = 0, off_e = 0, acc0 = 0;
    #pragma unroll
    for (int ee = 0; ee < E_NUM; ee++) {
        int c = g_cnt[ee];
        int tl = (c + 255) >> 8;
        if (e < 0) {
            if (mt < acc0 + tl) { e = ee; cnt_e = c; off_e = g_off[ee]; mt -= acc0; }
            else acc0 += tl;
        }
    }
    if (e < 0) return;
    int m0 = mt * 256;
    int bn0 = blockIdx.y * 128;

    extern __shared__ __align__(16) char sm[];
    uint32_t sbase = smem_u32(sm);

    int tid = threadIdx.x;
    int lane = tid & 31;
    int wid = tid >> 5;       // 0..15
    int wm = wid & 3;         // m 64-block (0..3)
    int wn = wid >> 2;        // n 32-block (0..3)

    bool warp_active = (m0 + wm * 64) < cnt_e;

    // ---- A: 2 cp.async 16B chunks/thread (256 rows x 64B = 16KB/stage) ----
    const char* aSrc[2];
    uint32_t stA[2];
    bool aVal[2];
    #pragma unroll
    for (int t = 0; t < 2; t++) {
        int idx = tid + t * 512;          // 0..1023
        int row = idx >> 2;               // 0..255
        int c16 = idx & 3;
        stA[t] = (uint32_t)(SM_A + row * ROWB + c16 * 16);
        int lm = m0 + row;
        aVal[t] = (lm < cnt_e);
        int safe = aVal[t] ? lm : 0;
        if (MODE == 1) {
            int tok = g_rowtok[off_e + safe];
            aSrc[t] = (const char*)(g_tnh + (size_t)tok * KD + c16 * 8);
        } else {
            aSrc[t] = (const char*)(g_h1h + (size_t)(off_e + safe) * KD + c16 * 8);
        }
    }
    // ---- B: 1 chunk/thread of 8 fp32 -> 16B fp16 (128 rows x 64B = 8KB/stage) ----
    int brow = tid >> 2;                  // 0..127
    int bc16 = tid & 3;
    uint32_t stB = (uint32_t)(SM_B + brow * ROWB + bc16 * 16);
    const float* bP = W + ((size_t)e * NTOT + bn0 + brow) * KD + bc16 * 8;

    uint32_t aoff = (uint32_t)(SM_A + (wm * 64 + (lane & 15)) * ROWB + (lane >> 4) * 16);
    uint32_t boff = (uint32_t)(SM_B + (wn * 32 + (lane & 7) + (lane >> 4) * 8) * ROWB
                               + ((lane >> 3) & 1) * 16);

    float acc[4][4][4];
    #pragma unroll
    for (int i = 0; i < 4; i++)
        #pragma unroll
        for (int j = 0; j < 4; j++)
            #pragma unroll
            for (int q = 0; q < 4; q++) acc[i][j][q] = 0.f;

    // ---- prologue ----
    float4 pB0, pB1;
    #pragma unroll
    for (int t = 0; t < 2; t++) if (aVal[t]) cp_async16(sbase + stA[t], aSrc[t]);
    cp_commit();
    pB0 = *(const float4*)(bP);
    pB1 = *(const float4*)(bP + 4);
    {
        uint4 bh;
        bh.x = pkh2(pB0.x, pB0.y);
        bh.y = pkh2(pB0.z, pB0.w);
        bh.z = pkh2(pB1.x, pB1.y);
        bh.w = pkh2(pB1.z, pB1.w);
        *(uint4*)(sm + stB) = bh;
    }
    cp_wait0();
    __syncthreads();

    for (int kt = 0; kt < NST; kt++) {
        uint32_t cOff = (kt & 1) * BUF_BYTES;
        if (kt + 1 < NST) {
            int kadv = (kt + 1) * 32;
            uint32_t nOff = ((kt + 1) & 1) * BUF_BYTES;
            #pragma unroll
            for (int t = 0; t < 2; t++)
                if (aVal[t]) cp_async16(sbase + nOff + stA[t], aSrc[t] + kadv * 2);
            cp_commit();
            pB0 = *(const float4*)(bP + kadv);
            pB1 = *(const float4*)(bP + kadv + 4);
        }
        if (warp_active) {
            #pragma unroll
            for (int ks = 0; ks < 2; ks++) {
                uint32_t ah[4][4];
                #pragma unroll
                for (int im = 0; im < 4; im++)
                    ldsm_x4(ah[im], sbase + cOff + aoff + im * (16 * ROWB) + ks * 32);
                #pragma unroll
                for (int in2 = 0; in2 < 2; in2++) {
                    uint32_t bfr[4];
                    ldsm_x4(bfr, sbase + cOff + boff + in2 * (16 * ROWB) + ks * 32);
                    #pragma unroll
                    for (int im = 0; im < 4; im++) {
                        mma16816(acc[im][2*in2],   ah[im], bfr);
                        mma16816(acc[im][2*in2+1], ah[im], bfr + 2);
                    }
                }
            }
        }
        if (kt + 1 < NST) {
            uint32_t nOff = ((kt + 1) & 1) * BUF_BYTES;
            uint4 bh;
            bh.x = pkh2(pB0.x, pB0.y);
            bh.y = pkh2(pB0.z, pB0.w);
            bh.z = pkh2(pB1.x, pB1.y);
            bh.w = pkh2(pB1.z, pB1.w);
            *(uint4*)(sm + nOff + stB) = bh;
            cp_wait0();
            __syncthreads();
        }
    }

    // ---------------- epilogue ----------------
    if (warp_active) {
        #pragma unroll
        for (int im = 0; im < 4; im++) {
            #pragma unroll
            for (int in = 0; in < 4; in++) {
                int r0 = m0 + wm * 64 + im * 16 + (lane >> 2);
                int c  = bn0 + wn * 32 + in * 8 + (lane & 3) * 2;
                const float* bp = bias + (size_t)e * NTOT + c;
                #pragma unroll
                for (int half = 0; half < 2; half++) {
                    int r = r0 + half * 8;
                    if (r >= cnt_e) continue;
                    int p = off_e + r;
                    float d0 = acc[im][in][half * 2 + 0];
                    float d1 = acc[im][in][half * 2 + 1];
                    if (MODE == 1) {
                        float glu = d0 + __ldg(bp);
                        float lin = d1 + __ldg(bp + 1);
                        glu = fminf(glu, 7.0f);
                        lin = fminf(fmaxf(lin, -7.0f), 7.0f);
                        float sig = 1.0f / (1.0f + expf(-1.702f * glu));
                        float h = glu * sig * (lin + 1.0f);
                        g_h1h[(size_t)p * I_DIM + (c >> 1)] = __float2half(h);
                    } else {
                        float w = g_roww[p];
                        float o0 = (d0 + __ldg(bp)) * w;
                        float o1 = (d1 + __ldg(bp + 1)) * w;
                        *(float2*)&g_h2[(size_t)p * H_DIM + c] = make_float2(o0, o1);
                    }
                }
            }
        }
    }
}

// ---------------- 5: combine ----------------
__global__ __launch_bounds__(256) void combine_kernel(
    const float* __restrict__ x, float* __restrict__ out)
{
    int t = blockIdx.x;
    int tid = threadIdx.x;
    int p0 = g_tokrows[t * TOPK + 0];
    int p1 = g_tokrows[t * TOPK + 1];
    int p2 = g_tokrows[t * TOPK + 2];
    int p3 = g_tokrows[t * TOPK + 3];
    const float4* xr = (const float4*)(x + (size_t)t * H_DIM);
    float4* orow = (float4*)(out + (size_t)t * H_DIM);
    const float4* a = (const float4*)(g_h2 + (size_t)p0 * H_DIM);
    const float4* b = (const float4*)(g_h2 + (size_t)p1 * H_DIM);
    const float4* c = (const float4*)(g_h2 + (size_t)p2 * H_DIM);
    const float4* d = (const float4*)(g_h2 + (size_t)p3 * H_DIM);
    #pragma unroll
    for (int r = 0; r < 2; r++) {
        int f = tid + r * 256;
        float4 v = xr[f];
        float4 q0 = a[f], q1 = b[f], q2 = c[f], q3 = d[f];
        v.x += q0.x + q1.x + q2.x + q3.x;
        v.y += q0.y + q1.y + q2.y + q3.y;
        v.z += q0.z + q1.z + q2.z + q3.z;
        v.w += q0.w + q1.w + q2.w + q3.w;
        orow[f] = v;
    }
}

// ---------------- launch ----------------
extern "C" void kernel_launch(void* const* d_in, const int* in_sizes, int n_in,
                              void* d_out, int out_size)
{
    const float* x     = (const float*)d_in[0];
    const float* scale = (const float*)d_in[1];
    const float* gk    = (const float*)d_in[2];
    const float* gb    = (const float*)d_in[3];
    const float* w1    = (const float*)d_in[4];
    const float* b1    = (const float*)d_in[5];
    const float* w2    = (const float*)d_in[6];
    const float* b2    = (const float*)d_in[7];
    float* out = (float*)d_out;

    cudaFuncSetAttribute(moe_mma_kernel<1>, cudaFuncAttributeMaxDynamicSharedMemorySize, DSMEM);
    cudaFuncSetAttribute(moe_mma_kernel<2>, cudaFuncAttributeMaxDynamicSharedMemorySize, DSMEM);

    rms_router_kernel<<<T_TOK, 256>>>(x, scale, gk, gb);
    route_kernel<<<1, 256>>>();
    // x = 256-row m-tiles (sum ceil(c_e/256) <= 48), y = n-tiles
    moe_mma_kernel<1><<<dim3(48, 2 * I_DIM / 128), 512, DSMEM>>>(w1, b1);
    moe_mma_kernel<2><<<dim3(48, H_DIM / 128), 512, DSMEM>>>(w2, b2);
    combine_kernel<<<T_TOK, 256>>>(x, out);
}

// round 13
// speedup vs baseline: 1.0757x; 1.0757x over previous
#include <cuda_runtime.h>
#include <cuda_fp16.h>
#include <math.h>
#include <stdint.h>

#define T_TOK 2048
#define H_DIM 2048
#define I_DIM 2048
#define E_NUM 16
#define TOPK  4
#define ROWS  (T_TOK*TOPK)

// ---------------- scratch ----------------
__device__ __half g_tnh[(size_t)T_TOK * H_DIM];
__device__ __half g_h1h[(size_t)ROWS * I_DIM];
__device__ float g_h2[(size_t)ROWS * H_DIM];
__device__ int   g_cnt[E_NUM];
__device__ int   g_off[E_NUM];
__device__ int   g_rowtok[ROWS];
__device__ float g_roww[ROWS];
__device__ int   g_tokrows[T_TOK * TOPK];
__device__ int   g_topidx[T_TOK * TOPK];
__device__ float g_topw[T_TOK * TOPK];

// ---------------- PTX helpers ----------------
__device__ __forceinline__ uint32_t smem_u32(const void* p) {
    uint32_t a;
    asm("{ .reg .u64 t; cvta.to.shared.u64 t, %1; cvt.u32.u64 %0, t; }" : "=r"(a) : "l"(p));
    return a;
}
__device__ __forceinline__ void ldsm_x4(uint32_t* r, uint32_t addr) {
    asm volatile("ldmatrix.sync.aligned.m8n8.x4.shared.b16 {%0,%1,%2,%3}, [%4];"
                 : "=r"(r[0]), "=r"(r[1]), "=r"(r[2]), "=r"(r[3]) : "r"(addr));
}
__device__ __forceinline__ void mma16816(float* d, const uint32_t* a, const uint32_t* b) {
    asm volatile("mma.sync.aligned.m16n8k16.row.col.f32.f16.f16.f32 "
                 "{%0,%1,%2,%3}, {%4,%5,%6,%7}, {%8,%9}, {%0,%1,%2,%3};"
                 : "+f"(d[0]), "+f"(d[1]), "+f"(d[2]), "+f"(d[3])
                 : "r"(a[0]), "r"(a[1]), "r"(a[2]), "r"(a[3]), "r"(b[0]), "r"(b[1]));
}
__device__ __forceinline__ uint32_t pkh2(float a, float b) {
    __half2 h = __floats2half2_rn(a, b);
    return *(uint32_t*)&h;
}
__device__ __forceinline__ void cp_async16(uint32_t dst, const void* src) {
    asm volatile("cp.async.cg.shared.global [%0], [%1], 16;" :: "r"(dst), "l"(src) : "memory");
}
__device__ __forceinline__ void cp_commit() {
    asm volatile("cp.async.commit_group;" ::: "memory");
}
__device__ __forceinline__ void cp_wait0() {
    asm volatile("cp.async.wait_group 0;" ::: "memory");
}

// ---------------- 1: fused RMSNorm + router ----------------
__global__ __launch_bounds__(256) void rms_router_kernel(
    const float* __restrict__ x, const float* __restrict__ scale,
    const float* __restrict__ gk, const float* __restrict__ gb)
{
    int t = blockIdx.x;
    int tid = threadIdx.x;
    const float* xr = x + (size_t)t * H_DIM;

    float4 v0 = *(const float4*)(xr + tid * 8);
    float4 v1 = *(const float4*)(xr + tid * 8 + 4);
    float ss = v0.x*v0.x + v0.y*v0.y + v0.z*v0.z + v0.w*v0.w
             + v1.x*v1.x + v1.y*v1.y + v1.z*v1.z + v1.w*v1.w;
    #pragma unroll
    for (int o = 16; o > 0; o >>= 1) ss += __shfl_down_sync(0xffffffffu, ss, o);
    __shared__ float warpsum[8];
    __shared__ float s_r;
    if ((tid & 31) == 0) warpsum[tid >> 5] = ss;
    __syncthreads();
    if (tid == 0) {
        float tot = 0.f;
        #pragma unroll
        for (int w = 0; w < 8; w++) tot += warpsum[w];
        s_r = 1.0f / sqrtf(tot / (float)H_DIM + 1e-5f);
    }
    __syncthreads();
    float r = s_r;

    float4 sc0 = *(const float4*)(scale + tid * 8);
    float4 sc1 = *(const float4*)(scale + tid * 8 + 4);
    float tn[8];
    tn[0] = v0.x*r*sc0.x; tn[1] = v0.y*r*sc0.y; tn[2] = v0.z*r*sc0.z; tn[3] = v0.w*r*sc0.w;
    tn[4] = v1.x*r*sc1.x; tn[5] = v1.y*r*sc1.y; tn[6] = v1.z*r*sc1.z; tn[7] = v1.w*r*sc1.w;

    __half hh[8];
    #pragma unroll
    for (int u = 0; u < 8; u++) hh[u] = __float2half(tn[u]);
    *(uint4*)(g_tnh + (size_t)t * H_DIM + tid * 8) = *(uint4*)hh;

    float ge[E_NUM];
    #pragma unroll
    for (int e = 0; e < E_NUM; e++) ge[e] = 0.f;
    #pragma unroll
    for (int u = 0; u < 8; u++) {
        const float4* wrow = (const float4*)(gk + (size_t)(tid * 8 + u) * E_NUM);
        float tv = tn[u];
        float4 a = wrow[0], b = wrow[1], c = wrow[2], d = wrow[3];
        ge[0]+=tv*a.x; ge[1]+=tv*a.y; ge[2]+=tv*a.z; ge[3]+=tv*a.w;
        ge[4]+=tv*b.x; ge[5]+=tv*b.y; ge[6]+=tv*b.z; ge[7]+=tv*b.w;
        ge[8]+=tv*c.x; ge[9]+=tv*c.y; ge[10]+=tv*c.z; ge[11]+=tv*c.w;
        ge[12]+=tv*d.x; ge[13]+=tv*d.y; ge[14]+=tv*d.z; ge[15]+=tv*d.w;
    }
    #pragma unroll
    for (int o = 16; o > 0; o >>= 1) {
        #pragma unroll
        for (int e = 0; e < E_NUM; e++) ge[e] += __shfl_down_sync(0xffffffffu, ge[e], o);
    }
    __shared__ float sg[8][E_NUM];
    if ((tid & 31) == 0) {
        #pragma unroll
        for (int e = 0; e < E_NUM; e++) sg[tid >> 5][e] = ge[e];
    }
    __syncthreads();
    __shared__ float s_logit[E_NUM];
    if (tid < E_NUM) {
        float v = gb[tid];
        #pragma unroll
        for (int w = 0; w < 8; w++) v += sg[w][tid];
        s_logit[tid] = v;
    }
    __syncthreads();
    if (tid == 0) {
        float vals[E_NUM];
        #pragma unroll
        for (int e = 0; e < E_NUM; e++) vals[e] = s_logit[e];
        int ids[TOPK]; float tv[TOPK];
        #pragma unroll
        for (int k = 0; k < TOPK; k++) {
            int bi = 0; float bv = -1e30f;
            #pragma unroll
            for (int e = 0; e < E_NUM; e++) if (vals[e] > bv) { bv = vals[e]; bi = e; }
            ids[k] = bi; tv[k] = bv; vals[bi] = -1e30f;
        }
        float m = tv[0], ex[TOPK], s = 0.f;
        #pragma unroll
        for (int k = 0; k < TOPK; k++) { ex[k] = expf(tv[k] - m); s += ex[k]; }
        float inv = 1.0f / s;
        #pragma unroll
        for (int k = 0; k < TOPK; k++) {
            g_topidx[t * TOPK + k] = ids[k];
            g_topw[t * TOPK + k]   = ex[k] * inv;
        }
    }
}

// ---------------- 2: route ----------------
__global__ __launch_bounds__(256) void route_kernel() {
    __shared__ int s_cnt[E_NUM];
    __shared__ int s_off[E_NUM];
    __shared__ int s_cur[E_NUM];
    int tid = threadIdx.x;
    if (tid < E_NUM) s_cnt[tid] = 0;
    __syncthreads();
    for (int i = tid; i < T_TOK * TOPK; i += 256)
        atomicAdd(&s_cnt[g_topidx[i]], 1);
    __syncthreads();
    if (tid == 0) {
        int acc = 0;
        for (int e = 0; e < E_NUM; e++) { s_off[e] = acc; s_cur[e] = acc; acc += s_cnt[e]; }
    }
    __syncthreads();
    if (tid < E_NUM) { g_cnt[tid] = s_cnt[tid]; g_off[tid] = s_off[tid]; }
    for (int i = tid; i < T_TOK * TOPK; i += 256) {
        int e = g_topidx[i];
        int pos = atomicAdd(&s_cur[e], 1);
        g_rowtok[pos] = i >> 2;
        g_roww[pos]   = g_topw[i];
        g_tokrows[i]  = pos;
    }
}

// ---------------- 3/4: grouped GEMMs: CTA 256m x 64n, 256 thr, 8 warps 4m x 2n ----------------
// Warp tile 64x32 (64 acc regs). A fp16 cp.async (4 chunks/thr); B fp32 LDG -> fp16 STS
// (1 chunk/thr). Same MACs/stage as 128x128 but 32% less L1 traffic; 2 CTAs/SM kept.
#define ROWB 80
#define SM_A 0
#define SM_B 20480
#define BUF_BYTES 25600
#define DSMEM (2 * BUF_BYTES)

template <int MODE>
__global__ __launch_bounds__(256, 2) void moe_mma_kernel(
    const float* __restrict__ W, const float* __restrict__ bias)
{
    constexpr int NTOT = (MODE == 1) ? 2 * I_DIM : H_DIM;
    constexpr int KD = 2048;
    constexpr int NST = KD / 32;   // 64 stages

    // blockIdx.x = 256-row m-tile (consecutive CTAs share B via L2)
    int mt = blockIdx.x;
    int e = -1, cnt_e = 0, off_e = 0, acc0 = 0;
    #pragma unroll
    for (int ee = 0; ee < E_NUM; ee++) {
        int c = g_cnt[ee];
        int tl = (c + 255) >> 8;
        if (e < 0) {
            if (mt < acc0 + tl) { e = ee; cnt_e = c; off_e = g_off[ee]; mt -= acc0; }
            else acc0 += tl;
        }
    }
    if (e < 0) return;
    int m0 = mt * 256;
    int bn0 = blockIdx.y * 64;

    extern __shared__ __align__(16) char sm[];
    uint32_t sbase = smem_u32(sm);

    int tid = threadIdx.x;
    int lane = tid & 31;
    int wid = tid >> 5;       // 0..7
    int wm = wid & 3;         // m 64-block (0..3)
    int wn = wid >> 2;        // n 32-block (0..1)

    bool warp_active = (m0 + wm * 64) < cnt_e;

    // ---- A: 4 cp.async 16B chunks/thread (256 rows x 64B = 16KB/stage) ----
    const char* aSrc[4];
    uint32_t stA[4];
    bool aVal[4];
    #pragma unroll
    for (int t = 0; t < 4; t++) {
        int idx = tid + t * 256;          // 0..1023
        int row = idx >> 2;               // 0..255
        int c16 = idx & 3;
        stA[t] = (uint32_t)(SM_A + row * ROWB + c16 * 16);
        int lm = m0 + row;
        aVal[t] = (lm < cnt_e);
        int safe = aVal[t] ? lm : 0;
        if (MODE == 1) {
            int tok = g_rowtok[off_e + safe];
            aSrc[t] = (const char*)(g_tnh + (size_t)tok * KD + c16 * 8);
        } else {
            aSrc[t] = (const char*)(g_h1h + (size_t)(off_e + safe) * KD + c16 * 8);
        }
    }
    // ---- B: 1 chunk/thread of 8 fp32 -> 16B fp16 (64 rows x 64B = 4KB/stage) ----
    int brow = tid >> 2;                  // 0..63
    int bc16 = tid & 3;
    uint32_t stB = (uint32_t)(SM_B + brow * ROWB + bc16 * 16);
    const float* bP = W + ((size_t)e * NTOT + bn0 + brow) * KD + bc16 * 8;

    uint32_t aoff = (uint32_t)(SM_A + (wm * 64 + (lane & 15)) * ROWB + (lane >> 4) * 16);
    uint32_t boff = (uint32_t)(SM_B + (wn * 32 + (lane & 7) + (lane >> 4) * 8) * ROWB
                               + ((lane >> 3) & 1) * 16);

    float acc[4][4][4];
    #pragma unroll
    for (int i = 0; i < 4; i++)
        #pragma unroll
        for (int j = 0; j < 4; j++)
            #pragma unroll
            for (int q = 0; q < 4; q++) acc[i][j][q] = 0.f;

    // ---- prologue ----
    float4 pB0, pB1;
    #pragma unroll
    for (int t = 0; t < 4; t++) if (aVal[t]) cp_async16(sbase + stA[t], aSrc[t]);
    cp_commit();
    pB0 = *(const float4*)(bP);
    pB1 = *(const float4*)(bP + 4);
    {
        uint4 bh;
        bh.x = pkh2(pB0.x, pB0.y);
        bh.y = pkh2(pB0.z, pB0.w);
        bh.z = pkh2(pB1.x, pB1.y);
        bh.w = pkh2(pB1.z, pB1.w);
        *(uint4*)(sm + stB) = bh;
    }
    cp_wait0();
    __syncthreads();

    for (int kt = 0; kt < NST; kt++) {
        uint32_t cOff = (kt & 1) * BUF_BYTES;
        if (kt + 1 < NST) {
            int kadv = (kt + 1) * 32;
            uint32_t nOff = ((kt + 1) & 1) * BUF_BYTES;
            #pragma unroll
            for (int t = 0; t < 4; t++)
                if (aVal[t]) cp_async16(sbase + nOff + stA[t], aSrc[t] + kadv * 2);
            cp_commit();
            pB0 = *(const float4*)(bP + kadv);
            pB1 = *(const float4*)(bP + kadv + 4);
        }
        if (warp_active) {
            #pragma unroll
            for (int ks = 0; ks < 2; ks++) {
                uint32_t ah[4][4];
                #pragma unroll
                for (int im = 0; im < 4; im++)
                    ldsm_x4(ah[im], sbase + cOff + aoff + im * (16 * ROWB) + ks * 32);
                #pragma unroll
                for (int in2 = 0; in2 < 2; in2++) {
                    uint32_t bfr[4];
                    ldsm_x4(bfr, sbase + cOff + boff + in2 * (16 * ROWB) + ks * 32);
                    #pragma unroll
                    for (int im = 0; im < 4; im++) {
                        mma16816(acc[im][2*in2],   ah[im], bfr);
                        mma16816(acc[im][2*in2+1], ah[im], bfr + 2);
                    }
                }
            }
        }
        if (kt + 1 < NST) {
            uint32_t nOff = ((kt + 1) & 1) * BUF_BYTES;
            uint4 bh;
            bh.x = pkh2(pB0.x, pB0.y);
            bh.y = pkh2(pB0.z, pB0.w);
            bh.z = pkh2(pB1.x, pB1.y);
            bh.w = pkh2(pB1.z, pB1.w);
            *(uint4*)(sm + nOff + stB) = bh;
            cp_wait0();
            __syncthreads();
        }
    }

    // ---------------- epilogue ----------------
    if (warp_active) {
        #pragma unroll
        for (int im = 0; im < 4; im++) {
            #pragma unroll
            for (int in = 0; in < 4; in++) {
                int r0 = m0 + wm * 64 + im * 16 + (lane >> 2);
                int c  = bn0 + wn * 32 + in * 8 + (lane & 3) * 2;
                const float* bp = bias + (size_t)e * NTOT + c;
                #pragma unroll
                for (int half = 0; half < 2; half++) {
                    int r = r0 + half * 8;
                    if (r >= cnt_e) continue;
                    int p = off_e + r;
                    float d0 = acc[im][in][half * 2 + 0];
                    float d1 = acc[im][in][half * 2 + 1];
                    if (MODE == 1) {
                        float glu = d0 + __ldg(bp);
                        float lin = d1 + __ldg(bp + 1);
                        glu = fminf(glu, 7.0f);
                        lin = fminf(fmaxf(lin, -7.0f), 7.0f);
                        float sig = 1.0f / (1.0f + expf(-1.702f * glu));
                        float h = glu * sig * (lin + 1.0f);
                        g_h1h[(size_t)p * I_DIM + (c >> 1)] = __float2half(h);
                    } else {
                        float w = g_roww[p];
                        float o0 = (d0 + __ldg(bp)) * w;
                        float o1 = (d1 + __ldg(bp + 1)) * w;
                        *(float2*)&g_h2[(size_t)p * H_DIM + c] = make_float2(o0, o1);
                    }
                }
            }
        }
    }
}

// ---------------- 5: combine ----------------
__global__ __launch_bounds__(256) void combine_kernel(
    const float* __restrict__ x, float* __restrict__ out)
{
    int t = blockIdx.x;
    int tid = threadIdx.x;
    int p0 = g_tokrows[t * TOPK + 0];
    int p1 = g_tokrows[t * TOPK + 1];
    int p2 = g_tokrows[t * TOPK + 2];
    int p3 = g_tokrows[t * TOPK + 3];
    const float4* xr = (const float4*)(x + (size_t)t * H_DIM);
    float4* orow = (float4*)(out + (size_t)t * H_DIM);
    const float4* a = (const float4*)(g_h2 + (size_t)p0 * H_DIM);
    const float4* b = (const float4*)(g_h2 + (size_t)p1 * H_DIM);
    const float4* c = (const float4*)(g_h2 + (size_t)p2 * H_DIM);
    const float4* d = (const float4*)(g_h2 + (size_t)p3 * H_DIM);
    #pragma unroll
    for (int r = 0; r < 2; r++) {
        int f = tid + r * 256;
        float4 v = xr[f];
        float4 q0 = a[f], q1 = b[f], q2 = c[f], q3 = d[f];
        v.x += q0.x + q1.x + q2.x + q3.x;
        v.y += q0.y + q1.y + q2.y + q3.y;
        v.z += q0.z + q1.z + q2.z + q3.z;
        v.w += q0.w + q1.w + q2.w + q3.w;
        orow[f] = v;
    }
}

// ---------------- launch ----------------
extern "C" void kernel_launch(void* const* d_in, const int* in_sizes, int n_in,
                              void* d_out, int out_size)
{
    const float* x     = (const float*)d_in[0];
    const float* scale = (const float*)d_in[1];
    const float* gk    = (const float*)d_in[2];
    const float* gb    = (const float*)d_in[3];
    const float* w1    = (const float*)d_in[4];
    const float* b1    = (const float*)d_in[5];
    const float* w2    = (const float*)d_in[6];
    const float* b2    = (const float*)d_in[7];
    float* out = (float*)d_out;

    cudaFuncSetAttribute(moe_mma_kernel<1>, cudaFuncAttributeMaxDynamicSharedMemorySize, DSMEM);
    cudaFuncSetAttribute(moe_mma_kernel<2>, cudaFuncAttributeMaxDynamicSharedMemorySize, DSMEM);

    rms_router_kernel<<<T_TOK, 256>>>(x, scale, gk, gb);
    route_kernel<<<1, 256>>>();
    // x = 256-row m-tiles (sum ceil(c_e/256) <= 48), y = 64-col n-tiles
    moe_mma_kernel<1><<<dim3(48, 2 * I_DIM / 64), 256, DSMEM>>>(w1, b1);
    moe_mma_kernel<2><<<dim3(48, H_DIM / 64), 256, DSMEM>>>(w2, b2);
    combine_kernel<<<T_TOK, 256>>>(x, out);
}

// round 14
// speedup vs baseline: 1.1623x; 1.0805x over previous
#include <cuda_runtime.h>
#include <cuda_fp16.h>
#include <math.h>
#include <stdint.h>

#define T_TOK 2048
#define H_DIM 2048
#define I_DIM 2048
#define E_NUM 16
#define TOPK  4
#define ROWS  (T_TOK*TOPK)

// ---------------- scratch ----------------
__device__ __half g_tnh[(size_t)T_TOK * H_DIM];
__device__ __half g_h1h[(size_t)ROWS * I_DIM];
__device__ float g_h2[(size_t)ROWS * H_DIM];
__device__ int   g_cnt[E_NUM];
__device__ int   g_off[E_NUM];
__device__ int   g_rowtok[ROWS];
__device__ float g_roww[ROWS];
__device__ int   g_tokrows[T_TOK * TOPK];
__device__ int   g_topidx[T_TOK * TOPK];
__device__ float g_topw[T_TOK * TOPK];

// ---------------- PTX helpers ----------------
__device__ __forceinline__ uint32_t smem_u32(const void* p) {
    uint32_t a;
    asm("{ .reg .u64 t; cvta.to.shared.u64 t, %1; cvt.u32.u64 %0, t; }" : "=r"(a) : "l"(p));
    return a;
}
__device__ __forceinline__ void ldsm_x4(uint32_t* r, uint32_t addr) {
    asm volatile("ldmatrix.sync.aligned.m8n8.x4.shared.b16 {%0,%1,%2,%3}, [%4];"
                 : "=r"(r[0]), "=r"(r[1]), "=r"(r[2]), "=r"(r[3]) : "r"(addr));
}
__device__ __forceinline__ void mma16816(float* d, const uint32_t* a, const uint32_t* b) {
    asm volatile("mma.sync.aligned.m16n8k16.row.col.f32.f16.f16.f32 "
                 "{%0,%1,%2,%3}, {%4,%5,%6,%7}, {%8,%9}, {%0,%1,%2,%3};"
                 : "+f"(d[0]), "+f"(d[1]), "+f"(d[2]), "+f"(d[3])
                 : "r"(a[0]), "r"(a[1]), "r"(a[2]), "r"(a[3]), "r"(b[0]), "r"(b[1]));
}
__device__ __forceinline__ uint32_t pkh2(float a, float b) {
    __half2 h = __floats2half2_rn(a, b);
    return *(uint32_t*)&h;
}
__device__ __forceinline__ void cp_async16(uint32_t dst, const void* src) {
    asm volatile("cp.async.cg.shared.global [%0], [%1], 16;" :: "r"(dst), "l"(src) : "memory");
}
__device__ __forceinline__ void cp_commit() {
    asm volatile("cp.async.commit_group;" ::: "memory");
}
__device__ __forceinline__ void cp_wait1() {
    asm volatile("cp.async.wait_group 1;" ::: "memory");
}

// ---------------- 1: fused RMSNorm + router ----------------
__global__ __launch_bounds__(256) void rms_router_kernel(
    const float* __restrict__ x, const float* __restrict__ scale,
    const float* __restrict__ gk, const float* __restrict__ gb)
{
    int t = blockIdx.x;
    int tid = threadIdx.x;
    const float* xr = x + (size_t)t * H_DIM;

    float4 v0 = *(const float4*)(xr + tid * 8);
    float4 v1 = *(const float4*)(xr + tid * 8 + 4);
    float ss = v0.x*v0.x + v0.y*v0.y + v0.z*v0.z + v0.w*v0.w
             + v1.x*v1.x + v1.y*v1.y + v1.z*v1.z + v1.w*v1.w;
    #pragma unroll
    for (int o = 16; o > 0; o >>= 1) ss += __shfl_down_sync(0xffffffffu, ss, o);
    __shared__ float warpsum[8];
    __shared__ float s_r;
    if ((tid & 31) == 0) warpsum[tid >> 5] = ss;
    __syncthreads();
    if (tid == 0) {
        float tot = 0.f;
        #pragma unroll
        for (int w = 0; w < 8; w++) tot += warpsum[w];
        s_r = 1.0f / sqrtf(tot / (float)H_DIM + 1e-5f);
    }
    __syncthreads();
    float r = s_r;

    float4 sc0 = *(const float4*)(scale + tid * 8);
    float4 sc1 = *(const float4*)(scale + tid * 8 + 4);
    float tn[8];
    tn[0] = v0.x*r*sc0.x; tn[1] = v0.y*r*sc0.y; tn[2] = v0.z*r*sc0.z; tn[3] = v0.w*r*sc0.w;
    tn[4] = v1.x*r*sc1.x; tn[5] = v1.y*r*sc1.y; tn[6] = v1.z*r*sc1.z; tn[7] = v1.w*r*sc1.w;

    __half hh[8];
    #pragma unroll
    for (int u = 0; u < 8; u++) hh[u] = __float2half(tn[u]);
    *(uint4*)(g_tnh + (size_t)t * H_DIM + tid * 8) = *(uint4*)hh;

    float ge[E_NUM];
    #pragma unroll
    for (int e = 0; e < E_NUM; e++) ge[e] = 0.f;
    #pragma unroll
    for (int u = 0; u < 8; u++) {
        const float4* wrow = (const float4*)(gk + (size_t)(tid * 8 + u) * E_NUM);
        float tv = tn[u];
        float4 a = wrow[0], b = wrow[1], c = wrow[2], d = wrow[3];
        ge[0]+=tv*a.x; ge[1]+=tv*a.y; ge[2]+=tv*a.z; ge[3]+=tv*a.w;
        ge[4]+=tv*b.x; ge[5]+=tv*b.y; ge[6]+=tv*b.z; ge[7]+=tv*b.w;
        ge[8]+=tv*c.x; ge[9]+=tv*c.y; ge[10]+=tv*c.z; ge[11]+=tv*c.w;
        ge[12]+=tv*d.x; ge[13]+=tv*d.y; ge[14]+=tv*d.z; ge[15]+=tv*d.w;
    }
    #pragma unroll
    for (int o = 16; o > 0; o >>= 1) {
        #pragma unroll
        for (int e = 0; e < E_NUM; e++) ge[e] += __shfl_down_sync(0xffffffffu, ge[e], o);
    }
    __shared__ float sg[8][E_NUM];
    if ((tid & 31) == 0) {
        #pragma unroll
        for (int e = 0; e < E_NUM; e++) sg[tid >> 5][e] = ge[e];
    }
    __syncthreads();
    __shared__ float s_logit[E_NUM];
    if (tid < E_NUM) {
        float v = gb[tid];
        #pragma unroll
        for (int w = 0; w < 8; w++) v += sg[w][tid];
        s_logit[tid] = v;
    }
    __syncthreads();
    if (tid == 0) {
        float vals[E_NUM];
        #pragma unroll
        for (int e = 0; e < E_NUM; e++) vals[e] = s_logit[e];
        int ids[TOPK]; float tv[TOPK];
        #pragma unroll
        for (int k = 0; k < TOPK; k++) {
            int bi = 0; float bv = -1e30f;
            #pragma unroll
            for (int e = 0; e < E_NUM; e++) if (vals[e] > bv) { bv = vals[e]; bi = e; }
            ids[k] = bi; tv[k] = bv; vals[bi] = -1e30f;
        }
        float m = tv[0], ex[TOPK], s = 0.f;
        #pragma unroll
        for (int k = 0; k < TOPK; k++) { ex[k] = expf(tv[k] - m); s += ex[k]; }
        float inv = 1.0f / s;
        #pragma unroll
        for (int k = 0; k < TOPK; k++) {
            g_topidx[t * TOPK + k] = ids[k];
            g_topw[t * TOPK + k]   = ex[k] * inv;
        }
    }
}

// ---------------- 2: route ----------------
__global__ __launch_bounds__(256) void route_kernel() {
    __shared__ int s_cnt[E_NUM];
    __shared__ int s_off[E_NUM];
    __shared__ int s_cur[E_NUM];
    int tid = threadIdx.x;
    if (tid < E_NUM) s_cnt[tid] = 0;
    __syncthreads();
    for (int i = tid; i < T_TOK * TOPK; i += 256)
        atomicAdd(&s_cnt[g_topidx[i]], 1);
    __syncthreads();
    if (tid == 0) {
        int acc = 0;
        for (int e = 0; e < E_NUM; e++) { s_off[e] = acc; s_cur[e] = acc; acc += s_cnt[e]; }
    }
    __syncthreads();
    if (tid < E_NUM) { g_cnt[tid] = s_cnt[tid]; g_off[tid] = s_off[tid]; }
    for (int i = tid; i < T_TOK * TOPK; i += 256) {
        int e = g_topidx[i];
        int pos = atomicAdd(&s_cur[e], 1);
        g_rowtok[pos] = i >> 2;
        g_roww[pos]   = g_topw[i];
        g_tokrows[i]  = pos;
    }
}

// ---------------- 3/4: grouped GEMMs (R11 shape + 3-stage cp.async ring) ----------------
// Tile 128x128x32. 8 warps 2(m)x4(n), warp tile 64x32. A via cp.async 2 stages ahead,
// wait_group 1 per stage. B fp32 LDG (1 stage ahead in regs) -> fp16 STS.
#define ROWB 80
#define SM_A 0
#define SM_B 10240
#define BUF_BYTES 20480
#define NBUF 3
#define DSMEM (NBUF * BUF_BYTES)

template <int MODE>
__global__ __launch_bounds__(256, 2) void moe_mma_kernel(
    const float* __restrict__ W, const float* __restrict__ bias)
{
    constexpr int NTOT = (MODE == 1) ? 2 * I_DIM : H_DIM;
    constexpr int KD = 2048;
    constexpr int NST = KD / 32;   // 64 stages

    // blockIdx.x = m-tile (consecutive CTAs share B via L2)
    int mt = blockIdx.x;
    int e = -1, cnt_e = 0, off_e = 0, acc0 = 0;
    #pragma unroll
    for (int ee = 0; ee < E_NUM; ee++) {
        int c = g_cnt[ee];
        int tl = (c + 127) >> 7;
        if (e < 0) {
            if (mt < acc0 + tl) { e = ee; cnt_e = c; off_e = g_off[ee]; mt -= acc0; }
            else acc0 += tl;
        }
    }
    if (e < 0) return;
    int m0 = mt * 128;
    int bn0 = blockIdx.y * 128;

    extern __shared__ __align__(16) char sm[];
    uint32_t sbase = smem_u32(sm);

    int tid = threadIdx.x;
    int lane = tid & 31;
    int wid = tid >> 5;
    int wm = wid & 1;
    int wn = wid >> 1;

    // ---- A: 2 cp.async 16B chunks/thread ----
    const char* aSrc[2];
    uint32_t stA[2];
    #pragma unroll
    for (int t = 0; t < 2; t++) {
        int cid = tid + t * 256;
        int row = cid >> 2;
        int c16 = cid & 3;
        stA[t] = (uint32_t)(SM_A + row * ROWB + c16 * 16);
        int lm = m0 + row;
        int safe = (lm < cnt_e) ? lm : 0;
        if (MODE == 1) {
            int tok = g_rowtok[off_e + safe];
            aSrc[t] = (const char*)(g_tnh + (size_t)tok * KD + c16 * 8);
        } else {
            aSrc[t] = (const char*)(g_h1h + (size_t)(off_e + safe) * KD + c16 * 8);
        }
    }
    // ---- B: 2 chunks/thread of 8 fp32 -> 16B fp16 ----
    const float* bP[2];
    uint32_t stB[2];
    #pragma unroll
    for (int t = 0; t < 2; t++) {
        int cid = tid + t * 256;
        int row = cid >> 2;
        int c16 = cid & 3;
        stB[t] = (uint32_t)(SM_B + row * ROWB + c16 * 16);
        bP[t] = W + ((size_t)e * NTOT + bn0 + row) * KD + c16 * 8;
    }

    uint32_t aoff = (uint32_t)(SM_A + (wm * 64 + (lane & 15)) * ROWB + (lane >> 4) * 16);
    uint32_t boff = (uint32_t)(SM_B + (wn * 32 + (lane & 7) + (lane >> 4) * 8) * ROWB
                               + ((lane >> 3) & 1) * 16);

    float acc[4][4][4];
    #pragma unroll
    for (int i = 0; i < 4; i++)
        #pragma unroll
        for (int j = 0; j < 4; j++)
            #pragma unroll
            for (int q = 0; q < 4; q++) acc[i][j][q] = 0.f;

    // ---- prologue ----
    // A stage 0 -> buf0 (group), A stage 1 -> buf1 (group)
    #pragma unroll
    for (int t = 0; t < 2; t++) cp_async16(sbase + stA[t], aSrc[t]);
    cp_commit();
    #pragma unroll
    for (int t = 0; t < 2; t++) cp_async16(sbase + BUF_BYTES + stA[t], aSrc[t] + 64);
    cp_commit();
    // B stage 0 -> STS buf0
    float4 pB0[2], pB1[2];
    #pragma unroll
    for (int t = 0; t < 2; t++) {
        pB0[t] = *(const float4*)(bP[t]);
        pB1[t] = *(const float4*)(bP[t] + 4);
    }
    #pragma unroll
    for (int t = 0; t < 2; t++) {
        uint4 bh;
        bh.x = pkh2(pB0[t].x, pB0[t].y);
        bh.y = pkh2(pB0[t].z, pB0[t].w);
        bh.z = pkh2(pB1[t].x, pB1[t].y);
        bh.w = pkh2(pB1[t].z, pB1[t].w);
        *(uint4*)(sm + stB[t]) = bh;
    }
    // B stage 1 -> regs
    #pragma unroll
    for (int t = 0; t < 2; t++) {
        pB0[t] = *(const float4*)(bP[t] + 32);
        pB1[t] = *(const float4*)(bP[t] + 36);
    }
    cp_wait1();          // A stage 0 complete (stage 1 may be in flight)
    __syncthreads();

    for (int kt = 0; kt < NST; kt++) {
        uint32_t cOff = (uint32_t)((kt % NBUF) * BUF_BYTES);

        // issue A prefetch for stage kt+2 into buf (kt+2)%3; always commit one group
        if (kt + 2 < NST) {
            uint32_t pOff = (uint32_t)(((kt + 2) % NBUF) * BUF_BYTES);
            int kadv = (kt + 2) * 64;    // bytes (32 halves)
            #pragma unroll
            for (int t = 0; t < 2; t++)
                cp_async16(sbase + pOff + stA[t], aSrc[t] + kadv);
        }
        cp_commit();

        // B: STS stage kt+1 (from regs) into buf (kt+1)%3, then LDG stage kt+2
        if (kt + 1 < NST) {
            uint32_t qOff = (uint32_t)(((kt + 1) % NBUF) * BUF_BYTES);
            #pragma unroll
            for (int t = 0; t < 2; t++) {
                uint4 bh;
                bh.x = pkh2(pB0[t].x, pB0[t].y);
                bh.y = pkh2(pB0[t].z, pB0[t].w);
                bh.z = pkh2(pB1[t].x, pB1[t].y);
                bh.w = pkh2(pB1[t].z, pB1[t].w);
                *(uint4*)(sm + qOff + stB[t]) = bh;
            }
            if (kt + 2 < NST) {
                int kadv = (kt + 2) * 32;
                #pragma unroll
                for (int t = 0; t < 2; t++) {
                    pB0[t] = *(const float4*)(bP[t] + kadv);
                    pB1[t] = *(const float4*)(bP[t] + kadv + 4);
                }
            }
        }

        // compute on buffer kt%3
        #pragma unroll
        for (int ks = 0; ks < 2; ks++) {
            uint32_t ah[4][4];
            #pragma unroll
            for (int im = 0; im < 4; im++)
                ldsm_x4(ah[im], sbase + cOff + aoff + im * (16 * ROWB) + ks * 32);
            #pragma unroll
            for (int in2 = 0; in2 < 2; in2++) {
                uint32_t bfr[4];
                ldsm_x4(bfr, sbase + cOff + boff + in2 * (16 * ROWB) + ks * 32);
                #pragma unroll
                for (int im = 0; im < 4; im++) {
                    mma16816(acc[im][2*in2],   ah[im], bfr);
                    mma16816(acc[im][2*in2+1], ah[im], bfr + 2);
                }
            }
        }

        if (kt + 1 < NST) {
            cp_wait1();           // A stage kt+1 complete (kt+2 still in flight)
            __syncthreads();
        }
    }

    // ---------------- epilogue ----------------
    #pragma unroll
    for (int im = 0; im < 4; im++) {
        #pragma unroll
        for (int in = 0; in < 4; in++) {
            int r0 = m0 + wm * 64 + im * 16 + (lane >> 2);
            int c  = bn0 + wn * 32 + in * 8 + (lane & 3) * 2;
            const float* bp = bias + (size_t)e * NTOT + c;
            #pragma unroll
            for (int half = 0; half < 2; half++) {
                int r = r0 + half * 8;
                if (r >= cnt_e) continue;
                int p = off_e + r;
                float d0 = acc[im][in][half * 2 + 0];
                float d1 = acc[im][in][half * 2 + 1];
                if (MODE == 1) {
                    float glu = d0 + __ldg(bp);
                    float lin = d1 + __ldg(bp + 1);
                    glu = fminf(glu, 7.0f);
                    lin = fminf(fmaxf(lin, -7.0f), 7.0f);
                    float sig = 1.0f / (1.0f + expf(-1.702f * glu));
                    float h = glu * sig * (lin + 1.0f);
                    g_h1h[(size_t)p * I_DIM + (c >> 1)] = __float2half(h);
                } else {
                    float w = g_roww[p];
                    float o0 = (d0 + __ldg(bp)) * w;
                    float o1 = (d1 + __ldg(bp + 1)) * w;
                    *(float2*)&g_h2[(size_t)p * H_DIM + c] = make_float2(o0, o1);
                }
            }
        }
    }
}

// ---------------- 5: combine ----------------
__global__ __launch_bounds__(256) void combine_kernel(
    const float* __restrict__ x, float* __restrict__ out)
{
    int t = blockIdx.x;
    int tid = threadIdx.x;
    int p0 = g_tokrows[t * TOPK + 0];
    int p1 = g_tokrows[t * TOPK + 1];
    int p2 = g_tokrows[t * TOPK + 2];
    int p3 = g_tokrows[t * TOPK + 3];
    const float4* xr = (const float4*)(x + (size_t)t * H_DIM);
    float4* orow = (float4*)(out + (size_t)t * H_DIM);
    const float4* a = (const float4*)(g_h2 + (size_t)p0 * H_DIM);
    const float4* b = (const float4*)(g_h2 + (size_t)p1 * H_DIM);
    const float4* c = (const float4*)(g_h2 + (size_t)p2 * H_DIM);
    const float4* d = (const float4*)(g_h2 + (size_t)p3 * H_DIM);
    #pragma unroll
    for (int r = 0; r < 2; r++) {
        int f = tid + r * 256;
        float4 v = xr[f];
        float4 q0 = a[f], q1 = b[f], q2 = c[f], q3 = d[f];
        v.x += q0.x + q1.x + q2.x + q3.x;
        v.y += q0.y + q1.y + q2.y + q3.y;
        v.z += q0.z + q1.z + q2.z + q3.z;
        v.w += q0.w + q1.w + q2.w + q3.w;
        orow[f] = v;
    }
}

// ---------------- launch ----------------
extern "C" void kernel_launch(void* const* d_in, const int* in_sizes, int n_in,
                              void* d_out, int out_size)
{
    const float* x     = (const float*)d_in[0];
    const float* scale = (const float*)d_in[1];
    const float* gk    = (const float*)d_in[2];
    const float* gb    = (const float*)d_in[3];
    const float* w1    = (const float*)d_in[4];
    const float* b1    = (const float*)d_in[5];
    const float* w2    = (const float*)d_in[6];
    const float* b2    = (const float*)d_in[7];
    float* out = (float*)d_out;

    cudaFuncSetAttribute(moe_mma_kernel<1>, cudaFuncAttributeMaxDynamicSharedMemorySize, DSMEM);
    cudaFuncSetAttribute(moe_mma_kernel<2>, cudaFuncAttributeMaxDynamicSharedMemorySize, DSMEM);

    rms_router_kernel<<<T_TOK, 256>>>(x, scale, gk, gb);
    route_kernel<<<1, 256>>>();
    moe_mma_kernel<1><<<dim3(80, 2 * I_DIM / 128), 256, DSMEM>>>(w1, b1);
    moe_mma_kernel<2><<<dim3(80, H_DIM / 128), 256, DSMEM>>>(w2, b2);
    combine_kernel<<<T_TOK, 256>>>(x, out);
}

// round 15
// speedup vs baseline: 1.1937x; 1.0270x over previous
#include <cuda_runtime.h>
#include <cuda_fp16.h>
#include <math.h>
#include <stdint.h>

#define T_TOK 2048
#define H_DIM 2048
#define I_DIM 2048
#define E_NUM 16
#define TOPK  4
#define ROWS  (T_TOK*TOPK)

// ---------------- scratch ----------------
__device__ __half g_tnh[(size_t)T_TOK * H_DIM];
__device__ __half g_h1h[(size_t)ROWS * I_DIM];
__device__ __half g_w2h[(size_t)E_NUM * H_DIM * I_DIM];   // 128 MB, filled during GEMM1
__device__ float g_h2[(size_t)ROWS * H_DIM];
__device__ int   g_cnt[E_NUM];
__device__ int   g_off[E_NUM];
__device__ int   g_rowtok[ROWS];
__device__ float g_roww[ROWS];
__device__ int   g_tokrows[T_TOK * TOPK];
__device__ int   g_topidx[T_TOK * TOPK];
__device__ float g_topw[T_TOK * TOPK];

// ---------------- PTX helpers ----------------
__device__ __forceinline__ uint32_t smem_u32(const void* p) {
    uint32_t a;
    asm("{ .reg .u64 t; cvta.to.shared.u64 t, %1; cvt.u32.u64 %0, t; }" : "=r"(a) : "l"(p));
    return a;
}
__device__ __forceinline__ void ldsm_x4(uint32_t* r, uint32_t addr) {
    asm volatile("ldmatrix.sync.aligned.m8n8.x4.shared.b16 {%0,%1,%2,%3}, [%4];"
                 : "=r"(r[0]), "=r"(r[1]), "=r"(r[2]), "=r"(r[3]) : "r"(addr));
}
__device__ __forceinline__ void mma16816(float* d, const uint32_t* a, const uint32_t* b) {
    asm volatile("mma.sync.aligned.m16n8k16.row.col.f32.f16.f16.f32 "
                 "{%0,%1,%2,%3}, {%4,%5,%6,%7}, {%8,%9}, {%0,%1,%2,%3};"
                 : "+f"(d[0]), "+f"(d[1]), "+f"(d[2]), "+f"(d[3])
                 : "r"(a[0]), "r"(a[1]), "r"(a[2]), "r"(a[3]), "r"(b[0]), "r"(b[1]));
}
__device__ __forceinline__ uint32_t pkh2(float a, float b) {
    __half2 h = __floats2half2_rn(a, b);
    return *(uint32_t*)&h;
}
__device__ __forceinline__ void cp_async16(uint32_t dst, const void* src) {
    asm volatile("cp.async.cg.shared.global [%0], [%1], 16;" :: "r"(dst), "l"(src) : "memory");
}
__device__ __forceinline__ void cp_commit() {
    asm volatile("cp.async.commit_group;" ::: "memory");
}
__device__ __forceinline__ void cp_wait0() {
    asm volatile("cp.async.wait_group 0;" ::: "memory");
}

// ---------------- 1: fused RMSNorm + router ----------------
__global__ __launch_bounds__(256) void rms_router_kernel(
    const float* __restrict__ x, const float* __restrict__ scale,
    const float* __restrict__ gk, const float* __restrict__ gb)
{
    int t = blockIdx.x;
    int tid = threadIdx.x;
    const float* xr = x + (size_t)t * H_DIM;

    float4 v0 = *(const float4*)(xr + tid * 8);
    float4 v1 = *(const float4*)(xr + tid * 8 + 4);
    float ss = v0.x*v0.x + v0.y*v0.y + v0.z*v0.z + v0.w*v0.w
             + v1.x*v1.x + v1.y*v1.y + v1.z*v1.z + v1.w*v1.w;
    #pragma unroll
    for (int o = 16; o > 0; o >>= 1) ss += __shfl_down_sync(0xffffffffu, ss, o);
    __shared__ float warpsum[8];
    __shared__ float s_r;
    if ((tid & 31) == 0) warpsum[tid >> 5] = ss;
    __syncthreads();
    if (tid == 0) {
        float tot = 0.f;
        #pragma unroll
        for (int w = 0; w < 8; w++) tot += warpsum[w];
        s_r = 1.0f / sqrtf(tot / (float)H_DIM + 1e-5f);
    }
    __syncthreads();
    float r = s_r;

    float4 sc0 = *(const float4*)(scale + tid * 8);
    float4 sc1 = *(const float4*)(scale + tid * 8 + 4);
    float tn[8];
    tn[0] = v0.x*r*sc0.x; tn[1] = v0.y*r*sc0.y; tn[2] = v0.z*r*sc0.z; tn[3] = v0.w*r*sc0.w;
    tn[4] = v1.x*r*sc1.x; tn[5] = v1.y*r*sc1.y; tn[6] = v1.z*r*sc1.z; tn[7] = v1.w*r*sc1.w;

    __half hh[8];
    #pragma unroll
    for (int u = 0; u < 8; u++) hh[u] = __float2half(tn[u]);
    *(uint4*)(g_tnh + (size_t)t * H_DIM + tid * 8) = *(uint4*)hh;

    float ge[E_NUM];
    #pragma unroll
    for (int e = 0; e < E_NUM; e++) ge[e] = 0.f;
    #pragma unroll
    for (int u = 0; u < 8; u++) {
        const float4* wrow = (const float4*)(gk + (size_t)(tid * 8 + u) * E_NUM);
        float tv = tn[u];
        float4 a = wrow[0], b = wrow[1], c = wrow[2], d = wrow[3];
        ge[0]+=tv*a.x; ge[1]+=tv*a.y; ge[2]+=tv*a.z; ge[3]+=tv*a.w;
        ge[4]+=tv*b.x; ge[5]+=tv*b.y; ge[6]+=tv*b.z; ge[7]+=tv*b.w;
        ge[8]+=tv*c.x; ge[9]+=tv*c.y; ge[10]+=tv*c.z; ge[11]+=tv*c.w;
        ge[12]+=tv*d.x; ge[13]+=tv*d.y; ge[14]+=tv*d.z; ge[15]+=tv*d.w;
    }
    #pragma unroll
    for (int o = 16; o > 0; o >>= 1) {
        #pragma unroll
        for (int e = 0; e < E_NUM; e++) ge[e] += __shfl_down_sync(0xffffffffu, ge[e], o);
    }
    __shared__ float sg[8][E_NUM];
    if ((tid & 31) == 0) {
        #pragma unroll
        for (int e = 0; e < E_NUM; e++) sg[tid >> 5][e] = ge[e];
    }
    __syncthreads();
    __shared__ float s_logit[E_NUM];
    if (tid < E_NUM) {
        float v = gb[tid];
        #pragma unroll
        for (int w = 0; w < 8; w++) v += sg[w][tid];
        s_logit[tid] = v;
    }
    __syncthreads();
    if (tid == 0) {
        float vals[E_NUM];
        #pragma unroll
        for (int e = 0; e < E_NUM; e++) vals[e] = s_logit[e];
        int ids[TOPK]; float tv[TOPK];
        #pragma unroll
        for (int k = 0; k < TOPK; k++) {
            int bi = 0; float bv = -1e30f;
            #pragma unroll
            for (int e = 0; e < E_NUM; e++) if (vals[e] > bv) { bv = vals[e]; bi = e; }
            ids[k] = bi; tv[k] = bv; vals[bi] = -1e30f;
        }
        float m = tv[0], ex[TOPK], s = 0.f;
        #pragma unroll
        for (int k = 0; k < TOPK; k++) { ex[k] = expf(tv[k] - m); s += ex[k]; }
        float inv = 1.0f / s;
        #pragma unroll
        for (int k = 0; k < TOPK; k++) {
            g_topidx[t * TOPK + k] = ids[k];
            g_topw[t * TOPK + k]   = ex[k] * inv;
        }
    }
}

// ---------------- 2: route ----------------
__global__ __launch_bounds__(256) void route_kernel() {
    __shared__ int s_cnt[E_NUM];
    __shared__ int s_off[E_NUM];
    __shared__ int s_cur[E_NUM];
    int tid = threadIdx.x;
    if (tid < E_NUM) s_cnt[tid] = 0;
    __syncthreads();
    for (int i = tid; i < T_TOK * TOPK; i += 256)
        atomicAdd(&s_cnt[g_topidx[i]], 1);
    __syncthreads();
    if (tid == 0) {
        int acc = 0;
        for (int e = 0; e < E_NUM; e++) { s_off[e] = acc; s_cur[e] = acc; acc += s_cnt[e]; }
    }
    __syncthreads();
    if (tid < E_NUM) { g_cnt[tid] = s_cnt[tid]; g_off[tid] = s_off[tid]; }
    for (int i = tid; i < T_TOK * TOPK; i += 256) {
        int e = g_topidx[i];
        int pos = atomicAdd(&s_cur[e], 1);
        g_rowtok[pos] = i >> 2;
        g_roww[pos]   = g_topw[i];
        g_tokrows[i]  = pos;
    }
}

// ---------------- 3: GEMM1 (R11 layout) + fused w2 fp32->fp16 converter CTAs ----------------
#define ROWB 80
#define SM_A 0
#define SM_B 10240
#define BUF_BYTES 20480
#define DSMEM (2 * BUF_BYTES)
#define MT1 80        // GEMM1 m-tile slots
#define CVT_X 8       // converter x-slots appended
#define NT1 (2 * I_DIM / 128)   // 32 n-tiles
#define CVT_CHUNKS (NT1 * CVT_X)             // 256 chunks
#define W2_ELEMS ((size_t)E_NUM * H_DIM * I_DIM)   // 67,108,864
#define CVT_F4_PER_CHUNK (W2_ELEMS / 4 / CVT_CHUNKS)  // 65536 float4 per chunk

__global__ __launch_bounds__(256, 2) void moe_mma1_kernel(
    const float* __restrict__ W, const float* __restrict__ bias,
    const float* __restrict__ W2src)
{
    constexpr int NTOT = 2 * I_DIM;
    constexpr int KD = 2048;
    constexpr int NST = KD / 32;

    // -------- converter CTAs --------
    if (blockIdx.x >= MT1) {
        int chunk = blockIdx.y * CVT_X + (blockIdx.x - MT1);      // 0..255
        const float4* src = (const float4*)W2src + (size_t)chunk * CVT_F4_PER_CHUNK;
        uint2* dst = (uint2*)g_w2h + (size_t)chunk * CVT_F4_PER_CHUNK;
        int tid = threadIdx.x;
        for (int i = tid; i < CVT_F4_PER_CHUNK; i += 256) {
            float4 v = src[i];
            uint2 o;
            o.x = pkh2(v.x, v.y);
            o.y = pkh2(v.z, v.w);
            dst[i] = o;
        }
        return;
    }

    // -------- GEMM path (identical to R11 MODE 1) --------
    int mt = blockIdx.x;
    int e = -1, cnt_e = 0, off_e = 0, acc0 = 0;
    #pragma unroll
    for (int ee = 0; ee < E_NUM; ee++) {
        int c = g_cnt[ee];
        int tl = (c + 127) >> 7;
        if (e < 0) {
            if (mt < acc0 + tl) { e = ee; cnt_e = c; off_e = g_off[ee]; mt -= acc0; }
            else acc0 += tl;
        }
    }
    if (e < 0) return;
    int m0 = mt * 128;
    int bn0 = blockIdx.y * 128;

    extern __shared__ __align__(16) char sm[];
    uint32_t sbase = smem_u32(sm);

    int tid = threadIdx.x;
    int lane = tid & 31;
    int wid = tid >> 5;
    int wm = wid & 1;
    int wn = wid >> 1;

    const char* aSrc[2];
    uint32_t stA[2];
    #pragma unroll
    for (int t = 0; t < 2; t++) {
        int cid = tid + t * 256;
        int row = cid >> 2;
        int c16 = cid & 3;
        stA[t] = (uint32_t)(SM_A + row * ROWB + c16 * 16);
        int lm = m0 + row;
        int safe = (lm < cnt_e) ? lm : 0;
        int tok = g_rowtok[off_e + safe];
        aSrc[t] = (const char*)(g_tnh + (size_t)tok * KD + c16 * 8);
    }
    const float* bP[2];
    uint32_t stB[2];
    #pragma unroll
    for (int t = 0; t < 2; t++) {
        int cid = tid + t * 256;
        int row = cid >> 2;
        int c16 = cid & 3;
        stB[t] = (uint32_t)(SM_B + row * ROWB + c16 * 16);
        bP[t] = W + ((size_t)e * NTOT + bn0 + row) * KD + c16 * 8;
    }

    uint32_t aoff = (uint32_t)(SM_A + (wm * 64 + (lane & 15)) * ROWB + (lane >> 4) * 16);
    uint32_t boff = (uint32_t)(SM_B + (wn * 32 + (lane & 7) + (lane >> 4) * 8) * ROWB
                               + ((lane >> 3) & 1) * 16);

    float acc[4][4][4];
    #pragma unroll
    for (int i = 0; i < 4; i++)
        #pragma unroll
        for (int j = 0; j < 4; j++)
            #pragma unroll
            for (int q = 0; q < 4; q++) acc[i][j][q] = 0.f;

    float4 pB0[2], pB1[2];
    #pragma unroll
    for (int t = 0; t < 2; t++) cp_async16(sbase + stA[t], aSrc[t]);
    cp_commit();
    #pragma unroll
    for (int t = 0; t < 2; t++) {
        pB0[t] = *(const float4*)(bP[t]);
        pB1[t] = *(const float4*)(bP[t] + 4);
    }
    #pragma unroll
    for (int t = 0; t < 2; t++) {
        uint4 bh;
        bh.x = pkh2(pB0[t].x, pB0[t].y);
        bh.y = pkh2(pB0[t].z, pB0[t].w);
        bh.z = pkh2(pB1[t].x, pB1[t].y);
        bh.w = pkh2(pB1[t].z, pB1[t].w);
        *(uint4*)(sm + stB[t]) = bh;
    }
    cp_wait0();
    __syncthreads();

    for (int kt = 0; kt < NST; kt++) {
        uint32_t cOff = (kt & 1) * BUF_BYTES;
        if (kt + 1 < NST) {
            int kadv = (kt + 1) * 32;
            uint32_t nOff = ((kt + 1) & 1) * BUF_BYTES;
            #pragma unroll
            for (int t = 0; t < 2; t++)
                cp_async16(sbase + nOff + stA[t], aSrc[t] + kadv * 2);
            cp_commit();
            #pragma unroll
            for (int t = 0; t < 2; t++) {
                pB0[t] = *(const float4*)(bP[t] + kadv);
                pB1[t] = *(const float4*)(bP[t] + kadv + 4);
            }
        }
        #pragma unroll
        for (int ks = 0; ks < 2; ks++) {
            uint32_t ah[4][4];
            #pragma unroll
            for (int im = 0; im < 4; im++)
                ldsm_x4(ah[im], sbase + cOff + aoff + im * (16 * ROWB) + ks * 32);
            #pragma unroll
            for (int in2 = 0; in2 < 2; in2++) {
                uint32_t bfr[4];
                ldsm_x4(bfr, sbase + cOff + boff + in2 * (16 * ROWB) + ks * 32);
                #pragma unroll
                for (int im = 0; im < 4; im++) {
                    mma16816(acc[im][2*in2],   ah[im], bfr);
                    mma16816(acc[im][2*in2+1], ah[im], bfr + 2);
                }
            }
        }
        if (kt + 1 < NST) {
            uint32_t nOff = ((kt + 1) & 1) * BUF_BYTES;
            #pragma unroll
            for (int t = 0; t < 2; t++) {
                uint4 bh;
                bh.x = pkh2(pB0[t].x, pB0[t].y);
                bh.y = pkh2(pB0[t].z, pB0[t].w);
                bh.z = pkh2(pB1[t].x, pB1[t].y);
                bh.w = pkh2(pB1[t].z, pB1[t].w);
                *(uint4*)(sm + nOff + stB[t]) = bh;
            }
            cp_wait0();
            __syncthreads();
        }
    }

    // epilogue: swiglu -> g_h1h
    #pragma unroll
    for (int im = 0; im < 4; im++) {
        #pragma unroll
        for (int in = 0; in < 4; in++) {
            int r0 = m0 + wm * 64 + im * 16 + (lane >> 2);
            int c  = bn0 + wn * 32 + in * 8 + (lane & 3) * 2;
            const float* bp = bias + (size_t)e * NTOT + c;
            #pragma unroll
            for (int half = 0; half < 2; half++) {
                int r = r0 + half * 8;
                if (r >= cnt_e) continue;
                int p = off_e + r;
                float glu = acc[im][in][half * 2 + 0] + __ldg(bp);
                float lin = acc[im][in][half * 2 + 1] + __ldg(bp + 1);
                glu = fminf(glu, 7.0f);
                lin = fminf(fmaxf(lin, -7.0f), 7.0f);
                float sig = 1.0f / (1.0f + expf(-1.702f * glu));
                float h = glu * sig * (lin + 1.0f);
                g_h1h[(size_t)p * I_DIM + (c >> 1)] = __float2half(h);
            }
        }
    }
}

// ---------------- 4: GEMM2 — both operands via cp.async (B = pre-converted fp16) ----------------
__global__ __launch_bounds__(256, 2) void moe_mma2_kernel(const float* __restrict__ bias)
{
    constexpr int NTOT = H_DIM;
    constexpr int KD = 2048;
    constexpr int NST = KD / 32;

    int mt = blockIdx.x;
    int e = -1, cnt_e = 0, off_e = 0, acc0 = 0;
    #pragma unroll
    for (int ee = 0; ee < E_NUM; ee++) {
        int c = g_cnt[ee];
        int tl = (c + 127) >> 7;
        if (e < 0) {
            if (mt < acc0 + tl) { e = ee; cnt_e = c; off_e = g_off[ee]; mt -= acc0; }
            else acc0 += tl;
        }
    }
    if (e < 0) return;
    int m0 = mt * 128;
    int bn0 = blockIdx.y * 128;

    extern __shared__ __align__(16) char sm[];
    uint32_t sbase = smem_u32(sm);

    int tid = threadIdx.x;
    int lane = tid & 31;
    int wid = tid >> 5;
    int wm = wid & 1;
    int wn = wid >> 1;

    // A: 2 cp.async chunks/thread from g_h1h
    const char* aSrc[2];
    uint32_t stA[2];
    #pragma unroll
    for (int t = 0; t < 2; t++) {
        int cid = tid + t * 256;
        int row = cid >> 2;
        int c16 = cid & 3;
        stA[t] = (uint32_t)(SM_A + row * ROWB + c16 * 16);
        int lm = m0 + row;
        int safe = (lm < cnt_e) ? lm : 0;
        aSrc[t] = (const char*)(g_h1h + (size_t)(off_e + safe) * KD + c16 * 8);
    }
    // B: 2 cp.async chunks/thread from g_w2h (fp16)
    const char* bSrc[2];
    uint32_t stB[2];
    #pragma unroll
    for (int t = 0; t < 2; t++) {
        int cid = tid + t * 256;
        int row = cid >> 2;
        int c16 = cid & 3;
        stB[t] = (uint32_t)(SM_B + row * ROWB + c16 * 16);
        bSrc[t] = (const char*)(g_w2h + ((size_t)e * NTOT + bn0 + row) * KD + c16 * 8);
    }

    uint32_t aoff = (uint32_t)(SM_A + (wm * 64 + (lane & 15)) * ROWB + (lane >> 4) * 16);
    uint32_t boff = (uint32_t)(SM_B + (wn * 32 + (lane & 7) + (lane >> 4) * 8) * ROWB
                               + ((lane >> 3) & 1) * 16);

    float acc[4][4][4];
    #pragma unroll
    for (int i = 0; i < 4; i++)
        #pragma unroll
        for (int j = 0; j < 4; j++)
            #pragma unroll
            for (int q = 0; q < 4; q++) acc[i][j][q] = 0.f;

    // prologue: stage 0
    #pragma unroll
    for (int t = 0; t < 2; t++) {
        cp_async16(sbase + stA[t], aSrc[t]);
        cp_async16(sbase + stB[t], bSrc[t]);
    }
    cp_commit();
    cp_wait0();
    __syncthreads();

    for (int kt = 0; kt < NST; kt++) {
        uint32_t cOff = (kt & 1) * BUF_BYTES;
        if (kt + 1 < NST) {
            int kbyte = (kt + 1) * 64;   // 32 halves = 64 bytes
            uint32_t nOff = ((kt + 1) & 1) * BUF_BYTES;
            #pragma unroll
            for (int t = 0; t < 2; t++) {
                cp_async16(sbase + nOff + stA[t], aSrc[t] + kbyte);
                cp_async16(sbase + nOff + stB[t], bSrc[t] + kbyte);
            }
            cp_commit();
        }
        #pragma unroll
        for (int ks = 0; ks < 2; ks++) {
            uint32_t ah[4][4];
            #pragma unroll
            for (int im = 0; im < 4; im++)
                ldsm_x4(ah[im], sbase + cOff + aoff + im * (16 * ROWB) + ks * 32);
            #pragma unroll
            for (int in2 = 0; in2 < 2; in2++) {
                uint32_t bfr[4];
                ldsm_x4(bfr, sbase + cOff + boff + in2 * (16 * ROWB) + ks * 32);
                #pragma unroll
                for (int im = 0; im < 4; im++) {
                    mma16816(acc[im][2*in2],   ah[im], bfr);
                    mma16816(acc[im][2*in2+1], ah[im], bfr + 2);
                }
            }
        }
        if (kt + 1 < NST) {
            cp_wait0();
            __syncthreads();
        }
    }

    // epilogue: bias + routing weight -> g_h2
    #pragma unroll
    for (int im = 0; im < 4; im++) {
        #pragma unroll
        for (int in = 0; in < 4; in++) {
            int r0 = m0 + wm * 64 + im * 16 + (lane >> 2);
            int c  = bn0 + wn * 32 + in * 8 + (lane & 3) * 2;
            const float* bp = bias + (size_t)e * NTOT + c;
            #pragma unroll
            for (int half = 0; half < 2; half++) {
                int r = r0 + half * 8;
                if (r >= cnt_e) continue;
                int p = off_e + r;
                float w = g_roww[p];
                float o0 = (acc[im][in][half * 2 + 0] + __ldg(bp)) * w;
                float o1 = (acc[im][in][half * 2 + 1] + __ldg(bp + 1)) * w;
                *(float2*)&g_h2[(size_t)p * H_DIM + c] = make_float2(o0, o1);
            }
        }
    }
}

// ---------------- 5: combine ----------------
__global__ __launch_bounds__(256) void combine_kernel(
    const float* __restrict__ x, float* __restrict__ out)
{
    int t = blockIdx.x;
    int tid = threadIdx.x;
    int p0 = g_tokrows[t * TOPK + 0];
    int p1 = g_tokrows[t * TOPK + 1];
    int p2 = g_tokrows[t * TOPK + 2];
    int p3 = g_tokrows[t * TOPK + 3];
    const float4* xr = (const float4*)(x + (size_t)t * H_DIM);
    float4* orow = (float4*)(out + (size_t)t * H_DIM);
    const float4* a = (const float4*)(g_h2 + (size_t)p0 * H_DIM);
    const float4* b = (const float4*)(g_h2 + (size_t)p1 * H_DIM);
    const float4* c = (const float4*)(g_h2 + (size_t)p2 * H_DIM);
    const float4* d = (const float4*)(g_h2 + (size_t)p3 * H_DIM);
    #pragma unroll
    for (int r = 0; r < 2; r++) {
        int f = tid + r * 256;
        float4 v = xr[f];
        float4 q0 = a[f], q1 = b[f], q2 = c[f], q3 = d[f];
        v.x += q0.x + q1.x + q2.x + q3.x;
        v.y += q0.y + q1.y + q2.y + q3.y;
        v.z += q0.z + q1.z + q2.z + q3.z;
        v.w += q0.w + q1.w + q2.w + q3.w;
        orow[f] = v;
    }
}

// ---------------- launch ----------------
extern "C" void kernel_launch(void* const* d_in, const int* in_sizes, int n_in,
                              void* d_out, int out_size)
{
    const float* x     = (const float*)d_in[0];
    const float* scale = (const float*)d_in[1];
    const float* gk    = (const float*)d_in[2];
    const float* gb    = (const float*)d_in[3];
    const float* w1    = (const float*)d_in[4];
    const float* b1    = (const float*)d_in[5];
    const float* w2    = (const float*)d_in[6];
    const float* b2    = (const float*)d_in[7];
    float* out = (float*)d_out;

    cudaFuncSetAttribute(moe_mma1_kernel, cudaFuncAttributeMaxDynamicSharedMemorySize, DSMEM);
    cudaFuncSetAttribute(moe_mma2_kernel, cudaFuncAttributeMaxDynamicSharedMemorySize, DSMEM);

    rms_router_kernel<<<T_TOK, 256>>>(x, scale, gk, gb);
    route_kernel<<<1, 256>>>();
    // GEMM1 (80 m-tile slots + 8 converter slots) x 32 n-tiles
    moe_mma1_kernel<<<dim3(MT1 + CVT_X, NT1), 256, DSMEM>>>(w1, b1, w2);
    // GEMM2: fp16 weights (converted during GEMM1), both operands cp.async
    moe_mma2_kernel<<<dim3(80, H_DIM / 128), 256, DSMEM>>>(b2);
    combine_kernel<<<T_TOK, 256>>>(x, out);
}

// round 16
// speedup vs baseline: 1.2151x; 1.0179x over previous
#include <cuda_runtime.h>
#include <cuda_fp16.h>
#include <math.h>
#include <stdint.h>

#define T_TOK 2048
#define H_DIM 2048
#define I_DIM 2048
#define E_NUM 16
#define TOPK  4
#define ROWS  (T_TOK*TOPK)

// ---------------- scratch ----------------
__device__ __half g_tnh[(size_t)T_TOK * H_DIM];
__device__ __half g_h1h[(size_t)ROWS * I_DIM];
__device__ __half g_w2h[(size_t)E_NUM * H_DIM * I_DIM];   // 128 MB, filled during GEMM1
__device__ float g_h2[(size_t)ROWS * H_DIM];
__device__ int   g_cnt[E_NUM];
__device__ int   g_off[E_NUM];
__device__ int   g_rowtok[ROWS];
__device__ float g_roww[ROWS];
__device__ int   g_tokrows[T_TOK * TOPK];
__device__ int   g_topidx[T_TOK * TOPK];
__device__ float g_topw[T_TOK * TOPK];

// ---------------- PTX helpers ----------------
__device__ __forceinline__ uint32_t smem_u32(const void* p) {
    uint32_t a;
    asm("{ .reg .u64 t; cvta.to.shared.u64 t, %1; cvt.u32.u64 %0, t; }" : "=r"(a) : "l"(p));
    return a;
}
__device__ __forceinline__ void ldsm_x4(uint32_t* r, uint32_t addr) {
    asm volatile("ldmatrix.sync.aligned.m8n8.x4.shared.b16 {%0,%1,%2,%3}, [%4];"
                 : "=r"(r[0]), "=r"(r[1]), "=r"(r[2]), "=r"(r[3]) : "r"(addr));
}
__device__ __forceinline__ void mma16816(float* d, const uint32_t* a, const uint32_t* b) {
    asm volatile("mma.sync.aligned.m16n8k16.row.col.f32.f16.f16.f32 "
                 "{%0,%1,%2,%3}, {%4,%5,%6,%7}, {%8,%9}, {%0,%1,%2,%3};"
                 : "+f"(d[0]), "+f"(d[1]), "+f"(d[2]), "+f"(d[3])
                 : "r"(a[0]), "r"(a[1]), "r"(a[2]), "r"(a[3]), "r"(b[0]), "r"(b[1]));
}
__device__ __forceinline__ uint32_t pkh2(float a, float b) {
    __half2 h = __floats2half2_rn(a, b);
    return *(uint32_t*)&h;
}
__device__ __forceinline__ void cp_async16(uint32_t dst, const void* src) {
    asm volatile("cp.async.cg.shared.global [%0], [%1], 16;" :: "r"(dst), "l"(src) : "memory");
}
__device__ __forceinline__ void cp_commit() {
    asm volatile("cp.async.commit_group;" ::: "memory");
}
__device__ __forceinline__ void cp_wait0() {
    asm volatile("cp.async.wait_group 0;" ::: "memory");
}

// ---------------- 1: fused RMSNorm + router ----------------
__global__ __launch_bounds__(256) void rms_router_kernel(
    const float* __restrict__ x, const float* __restrict__ scale,
    const float* __restrict__ gk, const float* __restrict__ gb)
{
    int t = blockIdx.x;
    int tid = threadIdx.x;
    const float* xr = x + (size_t)t * H_DIM;

    float4 v0 = *(const float4*)(xr + tid * 8);
    float4 v1 = *(const float4*)(xr + tid * 8 + 4);
    float ss = v0.x*v0.x + v0.y*v0.y + v0.z*v0.z + v0.w*v0.w
             + v1.x*v1.x + v1.y*v1.y + v1.z*v1.z + v1.w*v1.w;
    #pragma unroll
    for (int o = 16; o > 0; o >>= 1) ss += __shfl_down_sync(0xffffffffu, ss, o);
    __shared__ float warpsum[8];
    __shared__ float s_r;
    if ((tid & 31) == 0) warpsum[tid >> 5] = ss;
    __syncthreads();
    if (tid == 0) {
        float tot = 0.f;
        #pragma unroll
        for (int w = 0; w < 8; w++) tot += warpsum[w];
        s_r = 1.0f / sqrtf(tot / (float)H_DIM + 1e-5f);
    }
    __syncthreads();
    float r = s_r;

    float4 sc0 = *(const float4*)(scale + tid * 8);
    float4 sc1 = *(const float4*)(scale + tid * 8 + 4);
    float tn[8];
    tn[0] = v0.x*r*sc0.x; tn[1] = v0.y*r*sc0.y; tn[2] = v0.z*r*sc0.z; tn[3] = v0.w*r*sc0.w;
    tn[4] = v1.x*r*sc1.x; tn[5] = v1.y*r*sc1.y; tn[6] = v1.z*r*sc1.z; tn[7] = v1.w*r*sc1.w;

    __half hh[8];
    #pragma unroll
    for (int u = 0; u < 8; u++) hh[u] = __float2half(tn[u]);
    *(uint4*)(g_tnh + (size_t)t * H_DIM + tid * 8) = *(uint4*)hh;

    float ge[E_NUM];
    #pragma unroll
    for (int e = 0; e < E_NUM; e++) ge[e] = 0.f;
    #pragma unroll
    for (int u = 0; u < 8; u++) {
        const float4* wrow = (const float4*)(gk + (size_t)(tid * 8 + u) * E_NUM);
        float tv = tn[u];
        float4 a = wrow[0], b = wrow[1], c = wrow[2], d = wrow[3];
        ge[0]+=tv*a.x; ge[1]+=tv*a.y; ge[2]+=tv*a.z; ge[3]+=tv*a.w;
        ge[4]+=tv*b.x; ge[5]+=tv*b.y; ge[6]+=tv*b.z; ge[7]+=tv*b.w;
        ge[8]+=tv*c.x; ge[9]+=tv*c.y; ge[10]+=tv*c.z; ge[11]+=tv*c.w;
        ge[12]+=tv*d.x; ge[13]+=tv*d.y; ge[14]+=tv*d.z; ge[15]+=tv*d.w;
    }
    #pragma unroll
    for (int o = 16; o > 0; o >>= 1) {
        #pragma unroll
        for (int e = 0; e < E_NUM; e++) ge[e] += __shfl_down_sync(0xffffffffu, ge[e], o);
    }
    __shared__ float sg[8][E_NUM];
    if ((tid & 31) == 0) {
        #pragma unroll
        for (int e = 0; e < E_NUM; e++) sg[tid >> 5][e] = ge[e];
    }
    __syncthreads();
    __shared__ float s_logit[E_NUM];
    if (tid < E_NUM) {
        float v = gb[tid];
        #pragma unroll
        for (int w = 0; w < 8; w++) v += sg[w][tid];
        s_logit[tid] = v;
    }
    __syncthreads();
    if (tid == 0) {
        float vals[E_NUM];
        #pragma unroll
        for (int e = 0; e < E_NUM; e++) vals[e] = s_logit[e];
        int ids[TOPK]; float tv[TOPK];
        #pragma unroll
        for (int k = 0; k < TOPK; k++) {
            int bi = 0; float bv = -1e30f;
            #pragma unroll
            for (int e = 0; e < E_NUM; e++) if (vals[e] > bv) { bv = vals[e]; bi = e; }
            ids[k] = bi; tv[k] = bv; vals[bi] = -1e30f;
        }
        float m = tv[0], ex[TOPK], s = 0.f;
        #pragma unroll
        for (int k = 0; k < TOPK; k++) { ex[k] = expf(tv[k] - m); s += ex[k]; }
        float inv = 1.0f / s;
        #pragma unroll
        for (int k = 0; k < TOPK; k++) {
            g_topidx[t * TOPK + k] = ids[k];
            g_topw[t * TOPK + k]   = ex[k] * inv;
        }
    }
}

// ---------------- 2: route ----------------
__global__ __launch_bounds__(256) void route_kernel() {
    __shared__ int s_cnt[E_NUM];
    __shared__ int s_off[E_NUM];
    __shared__ int s_cur[E_NUM];
    int tid = threadIdx.x;
    if (tid < E_NUM) s_cnt[tid] = 0;
    __syncthreads();
    for (int i = tid; i < T_TOK * TOPK; i += 256)
        atomicAdd(&s_cnt[g_topidx[i]], 1);
    __syncthreads();
    if (tid == 0) {
        int acc = 0;
        for (int e = 0; e < E_NUM; e++) { s_off[e] = acc; s_cur[e] = acc; acc += s_cnt[e]; }
    }
    __syncthreads();
    if (tid < E_NUM) { g_cnt[tid] = s_cnt[tid]; g_off[tid] = s_off[tid]; }
    for (int i = tid; i < T_TOK * TOPK; i += 256) {
        int e = g_topidx[i];
        int pos = atomicAdd(&s_cur[e], 1);
        g_rowtok[pos] = i >> 2;
        g_roww[pos]   = g_topw[i];
        g_tokrows[i]  = pos;
    }
}

// ---------------- 3: GEMM1 (R11 layout) + fine-grained w2 converter CTAs ----------------
#define ROWB 80
#define SM_A 0
#define SM_B 10240
#define BUF_BYTES 20480
#define DSMEM1 (2 * BUF_BYTES)
#define MT1 80
#define CVT_X 32                              // fine-grained converter slots
#define NT1 (2 * I_DIM / 128)                 // 32 n-tiles
#define CVT_CHUNKS (NT1 * CVT_X)              // 1024 chunks
#define W2_ELEMS ((size_t)E_NUM * H_DIM * I_DIM)
#define CVT_F4_PER_CHUNK (W2_ELEMS / 4 / CVT_CHUNKS)   // 16384 float4 / chunk

__global__ __launch_bounds__(256, 2) void moe_mma1_kernel(
    const float* __restrict__ W, const float* __restrict__ bias,
    const float* __restrict__ W2src)
{
    constexpr int NTOT = 2 * I_DIM;
    constexpr int KD = 2048;
    constexpr int NST = KD / 32;

    // -------- converter CTAs (small, ~7us each) --------
    if (blockIdx.x >= MT1) {
        int chunk = blockIdx.y * CVT_X + (blockIdx.x - MT1);
        const float4* src = (const float4*)W2src + (size_t)chunk * CVT_F4_PER_CHUNK;
        uint2* dst = (uint2*)g_w2h + (size_t)chunk * CVT_F4_PER_CHUNK;
        int tid = threadIdx.x;
        #pragma unroll 4
        for (int i = tid; i < CVT_F4_PER_CHUNK; i += 256) {
            float4 v = src[i];
            uint2 o;
            o.x = pkh2(v.x, v.y);
            o.y = pkh2(v.z, v.w);
            dst[i] = o;
        }
        return;
    }

    // -------- GEMM path (R11 MODE 1) --------
    int mt = blockIdx.x;
    int e = -1, cnt_e = 0, off_e = 0, acc0 = 0;
    #pragma unroll
    for (int ee = 0; ee < E_NUM; ee++) {
        int c = g_cnt[ee];
        int tl = (c + 127) >> 7;
        if (e < 0) {
            if (mt < acc0 + tl) { e = ee; cnt_e = c; off_e = g_off[ee]; mt -= acc0; }
            else acc0 += tl;
        }
    }
    if (e < 0) return;
    int m0 = mt * 128;
    int bn0 = blockIdx.y * 128;

    extern __shared__ __align__(16) char sm[];
    uint32_t sbase = smem_u32(sm);

    int tid = threadIdx.x;
    int lane = tid & 31;
    int wid = tid >> 5;
    int wm = wid & 1;
    int wn = wid >> 1;

    const char* aSrc[2];
    uint32_t stA[2];
    #pragma unroll
    for (int t = 0; t < 2; t++) {
        int cid = tid + t * 256;
        int row = cid >> 2;
        int c16 = cid & 3;
        stA[t] = (uint32_t)(SM_A + row * ROWB + c16 * 16);
        int lm = m0 + row;
        int safe = (lm < cnt_e) ? lm : 0;
        int tok = g_rowtok[off_e + safe];
        aSrc[t] = (const char*)(g_tnh + (size_t)tok * KD + c16 * 8);
    }
    const float* bP[2];
    uint32_t stB[2];
    #pragma unroll
    for (int t = 0; t < 2; t++) {
        int cid = tid + t * 256;
        int row = cid >> 2;
        int c16 = cid & 3;
        stB[t] = (uint32_t)(SM_B + row * ROWB + c16 * 16);
        bP[t] = W + ((size_t)e * NTOT + bn0 + row) * KD + c16 * 8;
    }

    uint32_t aoff = (uint32_t)(SM_A + (wm * 64 + (lane & 15)) * ROWB + (lane >> 4) * 16);
    uint32_t boff = (uint32_t)(SM_B + (wn * 32 + (lane & 7) + (lane >> 4) * 8) * ROWB
                               + ((lane >> 3) & 1) * 16);

    float acc[4][4][4];
    #pragma unroll
    for (int i = 0; i < 4; i++)
        #pragma unroll
        for (int j = 0; j < 4; j++)
            #pragma unroll
            for (int q = 0; q < 4; q++) acc[i][j][q] = 0.f;

    float4 pB0[2], pB1[2];
    #pragma unroll
    for (int t = 0; t < 2; t++) cp_async16(sbase + stA[t], aSrc[t]);
    cp_commit();
    #pragma unroll
    for (int t = 0; t < 2; t++) {
        pB0[t] = *(const float4*)(bP[t]);
        pB1[t] = *(const float4*)(bP[t] + 4);
    }
    #pragma unroll
    for (int t = 0; t < 2; t++) {
        uint4 bh;
        bh.x = pkh2(pB0[t].x, pB0[t].y);
        bh.y = pkh2(pB0[t].z, pB0[t].w);
        bh.z = pkh2(pB1[t].x, pB1[t].y);
        bh.w = pkh2(pB1[t].z, pB1[t].w);
        *(uint4*)(sm + stB[t]) = bh;
    }
    cp_wait0();
    __syncthreads();

    for (int kt = 0; kt < NST; kt++) {
        uint32_t cOff = (kt & 1) * BUF_BYTES;
        if (kt + 1 < NST) {
            int kadv = (kt + 1) * 32;
            uint32_t nOff = ((kt + 1) & 1) * BUF_BYTES;
            #pragma unroll
            for (int t = 0; t < 2; t++)
                cp_async16(sbase + nOff + stA[t], aSrc[t] + kadv * 2);
            cp_commit();
            #pragma unroll
            for (int t = 0; t < 2; t++) {
                pB0[t] = *(const float4*)(bP[t] + kadv);
                pB1[t] = *(const float4*)(bP[t] + kadv + 4);
            }
        }
        #pragma unroll
        for (int ks = 0; ks < 2; ks++) {
            uint32_t ah[4][4];
            #pragma unroll
            for (int im = 0; im < 4; im++)
                ldsm_x4(ah[im], sbase + cOff + aoff + im * (16 * ROWB) + ks * 32);
            #pragma unroll
            for (int in2 = 0; in2 < 2; in2++) {
                uint32_t bfr[4];
                ldsm_x4(bfr, sbase + cOff + boff + in2 * (16 * ROWB) + ks * 32);
                #pragma unroll
                for (int im = 0; im < 4; im++) {
                    mma16816(acc[im][2*in2],   ah[im], bfr);
                    mma16816(acc[im][2*in2+1], ah[im], bfr + 2);
                }
            }
        }
        if (kt + 1 < NST) {
            uint32_t nOff = ((kt + 1) & 1) * BUF_BYTES;
            #pragma unroll
            for (int t = 0; t < 2; t++) {
                uint4 bh;
                bh.x = pkh2(pB0[t].x, pB0[t].y);
                bh.y = pkh2(pB0[t].z, pB0[t].w);
                bh.z = pkh2(pB1[t].x, pB1[t].y);
                bh.w = pkh2(pB1[t].z, pB1[t].w);
                *(uint4*)(sm + nOff + stB[t]) = bh;
            }
            cp_wait0();
            __syncthreads();
        }
    }

    // epilogue: swiglu -> g_h1h
    #pragma unroll
    for (int im = 0; im < 4; im++) {
        #pragma unroll
        for (int in = 0; in < 4; in++) {
            int r0 = m0 + wm * 64 + im * 16 + (lane >> 2);
            int c  = bn0 + wn * 32 + in * 8 + (lane & 3) * 2;
            const float* bp = bias + (size_t)e * NTOT + c;
            #pragma unroll
            for (int half = 0; half < 2; half++) {
                int r = r0 + half * 8;
                if (r >= cnt_e) continue;
                int p = off_e + r;
                float glu = acc[im][in][half * 2 + 0] + __ldg(bp);
                float lin = acc[im][in][half * 2 + 1] + __ldg(bp + 1);
                glu = fminf(glu, 7.0f);
                lin = fminf(fmaxf(lin, -7.0f), 7.0f);
                float sig = 1.0f / (1.0f + expf(-1.702f * glu));
                float h = glu * sig * (lin + 1.0f);
                g_h1h[(size_t)p * I_DIM + (c >> 1)] = __float2half(h);
            }
        }
    }
}

// ---------------- 4: GEMM2 — fp16 x fp16 via cp.async, BK=64 (32 stages) ----------------
#define ROWB2 144
#define SM_A2 0
#define SM_B2 18432                 // 128 * 144
#define BUF2  36864
#define DSMEM2 (2 * BUF2)

__global__ __launch_bounds__(256, 2) void moe_mma2_kernel(const float* __restrict__ bias)
{
    constexpr int NTOT = H_DIM;
    constexpr int KD = 2048;
    constexpr int NST = KD / 64;    // 32 stages

    int mt = blockIdx.x;
    int e = -1, cnt_e = 0, off_e = 0, acc0 = 0;
    #pragma unroll
    for (int ee = 0; ee < E_NUM; ee++) {
        int c = g_cnt[ee];
        int tl = (c + 127) >> 7;
        if (e < 0) {
            if (mt < acc0 + tl) { e = ee; cnt_e = c; off_e = g_off[ee]; mt -= acc0; }
            else acc0 += tl;
        }
    }
    if (e < 0) return;
    int m0 = mt * 128;
    int bn0 = blockIdx.y * 128;

    extern __shared__ __align__(16) char sm[];
    uint32_t sbase = smem_u32(sm);

    int tid = threadIdx.x;
    int lane = tid & 31;
    int wid = tid >> 5;
    int wm = wid & 1;
    int wn = wid >> 1;

    // A: 4 cp.async chunks/thread (128 rows x 128B = 16KB/stage)
    const char* aSrc[4];
    uint32_t stA[4];
    #pragma unroll
    for (int t = 0; t < 4; t++) {
        int idx = tid + t * 256;          // 0..1023
        int row = idx >> 3;               // 0..127
        int c16 = idx & 7;                // 0..7 (16B chunks, 128B row)
        stA[t] = (uint32_t)(SM_A2 + row * ROWB2 + c16 * 16);
        int lm = m0 + row;
        int safe = (lm < cnt_e) ? lm : 0;
        aSrc[t] = (const char*)(g_h1h + (size_t)(off_e + safe) * KD + c16 * 8);
    }
    // B: 4 cp.async chunks/thread from g_w2h
    const char* bSrc[4];
    uint32_t stB[4];
    #pragma unroll
    for (int t = 0; t < 4; t++) {
        int idx = tid + t * 256;
        int row = idx >> 3;
        int c16 = idx & 7;
        stB[t] = (uint32_t)(SM_B2 + row * ROWB2 + c16 * 16);
        bSrc[t] = (const char*)(g_w2h + ((size_t)e * NTOT + bn0 + row) * KD + c16 * 8);
    }

    uint32_t aoff = (uint32_t)(SM_A2 + (wm * 64 + (lane & 15)) * ROWB2 + (lane >> 4) * 16);
    uint32_t boff = (uint32_t)(SM_B2 + (wn * 32 + (lane & 7) + (lane >> 4) * 8) * ROWB2
                               + ((lane >> 3) & 1) * 16);

    float acc[4][4][4];
    #pragma unroll
    for (int i = 0; i < 4; i++)
        #pragma unroll
        for (int j = 0; j < 4; j++)
            #pragma unroll
            for (int q = 0; q < 4; q++) acc[i][j][q] = 0.f;

    // prologue: stage 0
    #pragma unroll
    for (int t = 0; t < 4; t++) {
        cp_async16(sbase + stA[t], aSrc[t]);
        cp_async16(sbase + stB[t], bSrc[t]);
    }
    cp_commit();
    cp_wait0();
    __syncthreads();

    for (int kt = 0; kt < NST; kt++) {
        uint32_t cOff = (kt & 1) * BUF2;
        if (kt + 1 < NST) {
            int kbyte = (kt + 1) * 128;   // 64 halves
            uint32_t nOff = ((kt + 1) & 1) * BUF2;
            #pragma unroll
            for (int t = 0; t < 4; t++) {
                cp_async16(sbase + nOff + stA[t], aSrc[t] + kbyte);
                cp_async16(sbase + nOff + stB[t], bSrc[t] + kbyte);
            }
            cp_commit();
        }
        #pragma unroll
        for (int ks = 0; ks < 4; ks++) {
            uint32_t ah[4][4];
            #pragma unroll
            for (int im = 0; im < 4; im++)
                ldsm_x4(ah[im], sbase + cOff + aoff + im * (16 * ROWB2) + ks * 32);
            #pragma unroll
            for (int in2 = 0; in2 < 2; in2++) {
                uint32_t bfr[4];
                ldsm_x4(bfr, sbase + cOff + boff + in2 * (16 * ROWB2) + ks * 32);
                #pragma unroll
                for (int im = 0; im < 4; im++) {
                    mma16816(acc[im][2*in2],   ah[im], bfr);
                    mma16816(acc[im][2*in2+1], ah[im], bfr + 2);
                }
            }
        }
        if (kt + 1 < NST) {
            cp_wait0();
            __syncthreads();
        }
    }

    // epilogue
    #pragma unroll
    for (int im = 0; im < 4; im++) {
        #pragma unroll
        for (int in = 0; in < 4; in++) {
            int r0 = m0 + wm * 64 + im * 16 + (lane >> 2);
            int c  = bn0 + wn * 32 + in * 8 + (lane & 3) * 2;
            const float* bp = bias + (size_t)e * NTOT + c;
            #pragma unroll
            for (int half = 0; half < 2; half++) {
                int r = r0 + half * 8;
                if (r >= cnt_e) continue;
                int p = off_e + r;
                float w = g_roww[p];
                float o0 = (acc[im][in][half * 2 + 0] + __ldg(bp)) * w;
                float o1 = (acc[im][in][half * 2 + 1] + __ldg(bp + 1)) * w;
                *(float2*)&g_h2[(size_t)p * H_DIM + c] = make_float2(o0, o1);
            }
        }
    }
}

// ---------------- 5: combine ----------------
__global__ __launch_bounds__(256) void combine_kernel(
    const float* __restrict__ x, float* __restrict__ out)
{
    int t = blockIdx.x;
    int tid = threadIdx.x;
    int p0 = g_tokrows[t * TOPK + 0];
    int p1 = g_tokrows[t * TOPK + 1];
    int p2 = g_tokrows[t * TOPK + 2];
    int p3 = g_tokrows[t * TOPK + 3];
    const float4* xr = (const float4*)(x + (size_t)t * H_DIM);
    float4* orow = (float4*)(out + (size_t)t * H_DIM);
    const float4* a = (const float4*)(g_h2 + (size_t)p0 * H_DIM);
    const float4* b = (const float4*)(g_h2 + (size_t)p1 * H_DIM);
    const float4* c = (const float4*)(g_h2 + (size_t)p2 * H_DIM);
    const float4* d = (const float4*)(g_h2 + (size_t)p3 * H_DIM);
    #pragma unroll
    for (int r = 0; r < 2; r++) {
        int f = tid + r * 256;
        float4 v = xr[f];
        float4 q0 = a[f], q1 = b[f], q2 = c[f], q3 = d[f];
        v.x += q0.x + q1.x + q2.x + q3.x;
        v.y += q0.y + q1.y + q2.y + q3.y;
        v.z += q0.z + q1.z + q2.z + q3.z;
        v.w += q0.w + q1.w + q2.w + q3.w;
        orow[f] = v;
    }
}

// ---------------- launch ----------------
extern "C" void kernel_launch(void* const* d_in, const int* in_sizes, int n_in,
                              void* d_out, int out_size)
{
    const float* x     = (const float*)d_in[0];
    const float* scale = (const float*)d_in[1];
    const float* gk    = (const float*)d_in[2];
    const float* gb    = (const float*)d_in[3];
    const float* w1    = (const float*)d_in[4];
    const float* b1    = (const float*)d_in[5];
    const float* w2    = (const float*)d_in[6];
    const float* b2    = (const float*)d_in[7];
    float* out = (float*)d_out;

    cudaFuncSetAttribute(moe_mma1_kernel, cudaFuncAttributeMaxDynamicSharedMemorySize, DSMEM1);
    cudaFuncSetAttribute(moe_mma2_kernel, cudaFuncAttributeMaxDynamicSharedMemorySize, DSMEM2);

    rms_router_kernel<<<T_TOK, 256>>>(x, scale, gk, gb);
    route_kernel<<<1, 256>>>();
    moe_mma1_kernel<<<dim3(MT1 + CVT_X, NT1), 256, DSMEM1>>>(w1, b1, w2);
    moe_mma2_kernel<<<dim3(80, H_DIM / 128), 256, DSMEM2>>>(b2);
    combine_kernel<<<T_TOK, 256>>>(x, out);
}